// round 8
// baseline (speedup 1.0000x reference)
#include <cuda_runtime.h>

#define M_ROWS 4096
#define D_MODEL 512
#define FF_DIM 2048
#define NQ (4096*512)

__device__ float g_scratch[5 * NQ + 4096 * 2048];

// ---------------------------------------------------------------------------
// tf32 helpers
// ---------------------------------------------------------------------------
__device__ __forceinline__ unsigned f2tf(float f) {
    unsigned r;
    asm("cvt.rna.tf32.f32 %0, %1;" : "=r"(r) : "f"(f));
    return r;
}

__device__ __forceinline__ void mma_tf32(float d[4], const unsigned a[4],
                                         const unsigned b0, const unsigned b1,
                                         const float c[4]) {
    asm volatile(
        "mma.sync.aligned.m16n8k8.row.col.f32.tf32.tf32.f32 "
        "{%0,%1,%2,%3}, {%4,%5,%6,%7}, {%8,%9}, {%10,%11,%12,%13};"
        : "=f"(d[0]), "=f"(d[1]), "=f"(d[2]), "=f"(d[3])
        : "r"(a[0]), "r"(a[1]), "r"(a[2]), "r"(a[3]),
          "r"(b0), "r"(b1),
          "f"(c[0]), "f"(c[1]), "f"(c[2]), "f"(c[3]));
}

// ---------------------------------------------------------------------------
// tf32 tensor-core GEMM — EXACT R3 configuration (proven fastest: 428us).
// Block tile 64x128, BK=32, 256 threads (8 warps as 2x4), warp tile 32x32.
// Single smem buffer, no prefetch. As[64][36], Bs[32][136] conflict-free.
// ---------------------------------------------------------------------------
__device__ __forceinline__ void gemm_core(
    const float* __restrict__ A, const float* __restrict__ W,
    const float* __restrict__ bias, const float* __restrict__ res,
    float* __restrict__ C, int M, int N, int K)
{
    __shared__ unsigned As[64 * 36];
    __shared__ unsigned Bs[32 * 136];

    const int tid  = threadIdx.x;
    const int lane = tid & 31;
    const int warp = tid >> 5;
    const int wm   = warp & 1;
    const int wn   = warp >> 1;
    const int gr   = lane >> 2;
    const int gc   = lane & 3;

    const int bm = blockIdx.y * 64;
    const int bn = blockIdx.x * 128;

    float acc[2][4][4] = {};

    for (int k0 = 0; k0 < K; k0 += 32) {
#pragma unroll
        for (int i = 0; i < 2; i++) {
            int m  = i * 32 + (tid >> 3);
            int c4 = (tid & 7) * 4;
            float4 v = *(const float4*)(A + (size_t)(bm + m) * K + k0 + c4);
            uint4 t = make_uint4(f2tf(v.x), f2tf(v.y), f2tf(v.z), f2tf(v.w));
            *(uint4*)&As[m * 36 + c4] = t;
        }
#pragma unroll
        for (int i = 0; i < 4; i++) {
            int r  = warp * 4 + i;
            int n4 = lane * 4;
            float4 v = *(const float4*)(W + (size_t)(k0 + r) * N + bn + n4);
            uint4 t = make_uint4(f2tf(v.x), f2tf(v.y), f2tf(v.z), f2tf(v.w));
            *(uint4*)&Bs[r * 136 + n4] = t;
        }
        __syncthreads();

#pragma unroll
        for (int ks = 0; ks < 4; ks++) {
            unsigned a[2][4], b[4][2];
#pragma unroll
            for (int mt = 0; mt < 2; mt++) {
                int row = wm * 32 + mt * 16 + gr;
                int col = ks * 8 + gc;
                a[mt][0] = As[row * 36 + col];
                a[mt][1] = As[(row + 8) * 36 + col];
                a[mt][2] = As[row * 36 + col + 4];
                a[mt][3] = As[(row + 8) * 36 + col + 4];
            }
#pragma unroll
            for (int nt = 0; nt < 4; nt++) {
                int bc = wn * 32 + nt * 8 + gr;
                int kr = ks * 8 + gc;
                b[nt][0] = Bs[kr * 136 + bc];
                b[nt][1] = Bs[(kr + 4) * 136 + bc];
            }
#pragma unroll
            for (int mt = 0; mt < 2; mt++)
#pragma unroll
                for (int nt = 0; nt < 4; nt++)
                    mma_tf32(acc[mt][nt], a[mt], b[nt][0], b[nt][1], acc[mt][nt]);
        }
        __syncthreads();
    }

#pragma unroll
    for (int mt = 0; mt < 2; mt++) {
#pragma unroll
        for (int nt = 0; nt < 4; nt++) {
            int r0  = bm + wm * 32 + mt * 16 + gr;
            int col = bn + wn * 32 + nt * 8 + 2 * gc;
            float v0 = acc[mt][nt][0];
            float v1 = acc[mt][nt][1];
            float v2 = acc[mt][nt][2];
            float v3 = acc[mt][nt][3];
            if (bias) {
                float b0 = bias[col], b1 = bias[col + 1];
                v0 += b0; v1 += b1; v2 += b0; v3 += b1;
            }
            if (res) {
                float2 r0v = *(const float2*)(res + (size_t)r0 * N + col);
                float2 r1v = *(const float2*)(res + (size_t)(r0 + 8) * N + col);
                v0 += r0v.x; v1 += r0v.y; v2 += r1v.x; v3 += r1v.y;
            }
            *(float2*)(C + (size_t)r0 * N + col)       = make_float2(v0, v1);
            *(float2*)(C + (size_t)(r0 + 8) * N + col) = make_float2(v2, v3);
        }
    }
}

__global__ __launch_bounds__(256) void gemm_one(
    const float* __restrict__ A, const float* __restrict__ W,
    const float* __restrict__ bias, const float* __restrict__ res,
    float* __restrict__ C, int M, int N, int K)
{
    gemm_core(A, W, bias, res, C, M, N, K);
}

__global__ __launch_bounds__(256) void gemm_qkv(
    const float* __restrict__ Q, const float* __restrict__ K_,
    const float* __restrict__ V,
    const float* __restrict__ Wq, const float* __restrict__ Wk,
    const float* __restrict__ Wv,
    float* __restrict__ gq, float* __restrict__ gk, float* __restrict__ gv,
    int M, int N, int K)
{
    int z = blockIdx.z;
    const float* A = (z == 0) ? Q : (z == 1) ? K_ : V;
    const float* W = (z == 0) ? Wq : (z == 1) ? Wk : Wv;
    float* C       = (z == 0) ? gq : (z == 1) ? gk : gv;
    gemm_core(A, W, nullptr, nullptr, C, M, N, K);
}

// ---------------------------------------------------------------------------
// Tensor-core tf32 flash attention, no-max softmax (scores bounded; plain
// exp is mathematically identical). Denominator reduced once at the end.
// ---------------------------------------------------------------------------
#define QS_STRIDE 68
#define KS_STRIDE 68
#define VS_STRIDE 72
#define ATTN_SMEM ((128*QS_STRIDE + 64*KS_STRIDE + 64*VS_STRIDE) * 4)

__global__ __launch_bounds__(256) void attn_tc(
    const float* __restrict__ qp, const float* __restrict__ kp,
    const float* __restrict__ vp, float* __restrict__ op)
{
    extern __shared__ unsigned smem[];
    unsigned* Qs = smem;                       // 128 x 68 (also P staging)
    unsigned* Ks = Qs + 128 * QS_STRIDE;       // 64 x 68
    unsigned* Vs = Ks + 64 * KS_STRIDE;        // 64 x 72

    const int tid  = threadIdx.x;
    const int lane = tid & 31;
    const int warp = tid >> 5;
    const int gr   = lane >> 2;
    const int gc   = lane & 3;
    const int g    = blockIdx.y;
    const int q0   = blockIdx.x * 128;
    const float scale = 0.04419417382415922f;  // 1/sqrt(512)

    const float* qg = qp + ((size_t)g * 2048 + q0) * 64;
#pragma unroll
    for (int i = 0; i < 8; i++) {
        int idx = tid + i * 256;
        int row = idx >> 4, c4 = (idx & 15) * 4;
        float4 t = *(const float4*)(qg + (size_t)row * 64 + c4);
        uint4 u = make_uint4(f2tf(t.x * scale), f2tf(t.y * scale),
                             f2tf(t.z * scale), f2tf(t.w * scale));
        *(uint4*)&Qs[row * QS_STRIDE + c4] = u;
    }
    __syncthreads();

    unsigned qa[8][4];
    const int r = warp * 16 + gr;
#pragma unroll
    for (int kk = 0; kk < 8; kk++) {
        qa[kk][0] = Qs[r * QS_STRIDE + kk * 8 + gc];
        qa[kk][1] = Qs[(r + 8) * QS_STRIDE + kk * 8 + gc];
        qa[kk][2] = Qs[r * QS_STRIDE + kk * 8 + gc + 4];
        qa[kk][3] = Qs[(r + 8) * QS_STRIDE + kk * 8 + gc + 4];
    }

    float oacc[8][4];
#pragma unroll
    for (int nt = 0; nt < 8; nt++)
#pragma unroll
        for (int i = 0; i < 4; i++) oacc[nt][i] = 0.f;
    float psum0 = 0.f, psum1 = 0.f;

    for (int kt = 0; kt < 32; kt++) {
        __syncthreads();
        const float* kg = kp + ((size_t)g * 2048 + kt * 64) * 64;
        const float* vg = vp + ((size_t)g * 2048 + kt * 64) * 64;
#pragma unroll
        for (int i = 0; i < 4; i++) {
            int idx = tid + i * 256;
            int row = idx >> 4, c4 = (idx & 15) * 4;
            float4 a = *(const float4*)(kg + (size_t)row * 64 + c4);
            *(uint4*)&Ks[row * KS_STRIDE + c4] =
                make_uint4(f2tf(a.x), f2tf(a.y), f2tf(a.z), f2tf(a.w));
            float4 b = *(const float4*)(vg + (size_t)row * 64 + c4);
            *(uint4*)&Vs[row * VS_STRIDE + c4] =
                make_uint4(f2tf(b.x), f2tf(b.y), f2tf(b.z), f2tf(b.w));
        }
        __syncthreads();

        float sacc[8][4];
#pragma unroll
        for (int nt = 0; nt < 8; nt++)
#pragma unroll
            for (int i = 0; i < 4; i++) sacc[nt][i] = 0.f;
#pragma unroll
        for (int kk = 0; kk < 8; kk++) {
#pragma unroll
            for (int nt = 0; nt < 8; nt++) {
                unsigned b0 = Ks[(nt * 8 + gr) * KS_STRIDE + kk * 8 + gc];
                unsigned b1 = Ks[(nt * 8 + gr) * KS_STRIDE + kk * 8 + gc + 4];
                mma_tf32(sacc[nt], qa[kk], b0, b1, sacc[nt]);
            }
        }

#pragma unroll
        for (int nt = 0; nt < 8; nt++) {
            float p00 = __expf(sacc[nt][0]);
            float p01 = __expf(sacc[nt][1]);
            float p10 = __expf(sacc[nt][2]);
            float p11 = __expf(sacc[nt][3]);
            psum0 += p00 + p01;
            psum1 += p10 + p11;
            *(uint2*)&Qs[r * QS_STRIDE + nt * 8 + 2 * gc] =
                make_uint2(f2tf(p00), f2tf(p01));
            *(uint2*)&Qs[(r + 8) * QS_STRIDE + nt * 8 + 2 * gc] =
                make_uint2(f2tf(p10), f2tf(p11));
        }
        __syncwarp();

#pragma unroll
        for (int kk = 0; kk < 8; kk++) {
            unsigned pa[4];
            pa[0] = Qs[r * QS_STRIDE + kk * 8 + gc];
            pa[1] = Qs[(r + 8) * QS_STRIDE + kk * 8 + gc];
            pa[2] = Qs[r * QS_STRIDE + kk * 8 + gc + 4];
            pa[3] = Qs[(r + 8) * QS_STRIDE + kk * 8 + gc + 4];
#pragma unroll
            for (int nt = 0; nt < 8; nt++) {
                unsigned b0 = Vs[(kk * 8 + gc) * VS_STRIDE + nt * 8 + gr];
                unsigned b1 = Vs[(kk * 8 + gc + 4) * VS_STRIDE + nt * 8 + gr];
                mma_tf32(oacc[nt], pa, b0, b1, oacc[nt]);
            }
        }
    }

#pragma unroll
    for (int off = 1; off < 4; off <<= 1) {
        psum0 += __shfl_xor_sync(0xffffffffu, psum0, off);
        psum1 += __shfl_xor_sync(0xffffffffu, psum1, off);
    }
    float inv0 = 1.f / psum0;
    float inv1 = 1.f / psum1;
    int rr = q0 + warp * 16 + gr;
    float* og = op + ((size_t)g * 2048 + rr) * 64;
#pragma unroll
    for (int nt = 0; nt < 8; nt++) {
        *(float2*)(og + nt * 8 + 2 * gc) =
            make_float2(oacc[nt][0] * inv0, oacc[nt][1] * inv0);
        *(float2*)(og + 8 * 64 + nt * 8 + 2 * gc) =
            make_float2(oacc[nt][2] * inv1, oacc[nt][3] * inv1);
    }
}

// ---------------------------------------------------------------------------
// Vectorized in-place layernorm: 128 threads/row, float4 per thread.
// ---------------------------------------------------------------------------
__global__ __launch_bounds__(128) void ln512v(
    float* __restrict__ x, const float* __restrict__ gamma,
    const float* __restrict__ beta)
{
    const int row = blockIdx.x;
    const int tid = threadIdx.x;
    float4* p = (float4*)(x + (size_t)row * 512);
    float4 v = p[tid];
    float s  = v.x + v.y + v.z + v.w;
    float sq = v.x * v.x + v.y * v.y + v.z * v.z + v.w * v.w;
#pragma unroll
    for (int off = 16; off > 0; off >>= 1) {
        s  += __shfl_xor_sync(0xffffffffu, s, off);
        sq += __shfl_xor_sync(0xffffffffu, sq, off);
    }
    __shared__ float ws[4], wq[4];
    __shared__ float stats[2];
    if ((tid & 31) == 0) { ws[tid >> 5] = s; wq[tid >> 5] = sq; }
    __syncthreads();
    if (tid == 0) {
        float S = ws[0] + ws[1] + ws[2] + ws[3];
        float SQ = wq[0] + wq[1] + wq[2] + wq[3];
        float mu  = S * (1.f / 512.f);
        float var = SQ * (1.f / 512.f) - mu * mu;
        stats[0] = mu;
        stats[1] = rsqrtf(var + 1e-5f);
    }
    __syncthreads();
    float mu = stats[0], inv = stats[1];
    float4 gv = ((const float4*)gamma)[tid];
    float4 bv = ((const float4*)beta)[tid];
    p[tid] = make_float4((v.x - mu) * inv * gv.x + bv.x,
                         (v.y - mu) * inv * gv.y + bv.y,
                         (v.z - mu) * inv * gv.z + bv.z,
                         (v.w - mu) * inv * gv.w + bv.w);
}

// ---------------------------------------------------------------------------
extern "C" void kernel_launch(void* const* d_in, const int* in_sizes, int n_in,
                              void* d_out, int out_size)
{
    (void)in_sizes; (void)n_in; (void)out_size;
    const float* Q     = (const float*)d_in[0];
    const float* K     = (const float*)d_in[1];
    const float* V     = (const float*)d_in[2];
    const float* Wq    = (const float*)d_in[4];
    const float* Wk    = (const float*)d_in[5];
    const float* Wv    = (const float*)d_in[6];
    const float* Wo    = (const float*)d_in[7];
    const float* bo    = (const float*)d_in[8];
    const float* gamma = (const float*)d_in[9];
    const float* beta  = (const float*)d_in[10];
    const float* W1    = (const float*)d_in[11];
    const float* b1    = (const float*)d_in[12];
    const float* W2    = (const float*)d_in[13];
    const float* b2    = (const float*)d_in[14];
    float* out = (float*)d_out;

    float* base = nullptr;
    cudaGetSymbolAddress((void**)&base, g_scratch);
    float* gq    = base;
    float* gk    = base + (size_t)NQ;
    float* gv    = base + (size_t)2 * NQ;
    float* gattn = base + (size_t)3 * NQ;
    float* gZ    = base + (size_t)4 * NQ;
    float* gff   = base + (size_t)5 * NQ;

    cudaFuncSetAttribute(attn_tc,
                         cudaFuncAttributeMaxDynamicSharedMemorySize,
                         ATTN_SMEM);

    // QKV projections (fused, 768 blocks of 64x128)
    gemm_qkv<<<dim3(D_MODEL / 128, M_ROWS / 64, 3), 256>>>(
        Q, K, V, Wq, Wk, Wv, gq, gk, gv, M_ROWS, D_MODEL, D_MODEL);

    // Tensor-core attention over reinterpreted [16, 2048, 64]
    attn_tc<<<dim3(16, 16), 256, ATTN_SMEM>>>(gq, gk, gv, gattn);

    // Output projection + bias + residual (X = V), then LN -> Z
    gemm_one<<<dim3(D_MODEL / 128, M_ROWS / 64), 256>>>(
        gattn, Wo, bo, V, gZ, M_ROWS, D_MODEL, D_MODEL);
    ln512v<<<M_ROWS, 128>>>(gZ, gamma, beta);

    // FFN (no activation in the reference)
    gemm_one<<<dim3(FF_DIM / 128, M_ROWS / 64), 256>>>(
        gZ, W1, b1, nullptr, gff, M_ROWS, FF_DIM, D_MODEL);
    gemm_one<<<dim3(D_MODEL / 128, M_ROWS / 64), 256>>>(
        gff, W2, b2, gZ, out, M_ROWS, D_MODEL, FF_DIM);
    ln512v<<<M_ROWS, 128>>>(out, gamma, beta);
}

// round 9
// speedup vs baseline: 1.5630x; 1.5630x over previous
#include <cuda_runtime.h>
#include <cuda_fp16.h>

#define M_ROWS 4096
#define D_MODEL 512
#define FF_DIM 2048
#define NQ (4096*512)

__device__ float g_scratch[5 * NQ + 4096 * 2048];

// ---------------------------------------------------------------------------
// fp16 helpers
// ---------------------------------------------------------------------------
__device__ __forceinline__ unsigned h2pack(float lo, float hi) {
    __half2 h = __floats2half2_rn(lo, hi);   // .x = lo half
    return *(unsigned*)&h;
}

__device__ __forceinline__ void mma_f16(float d[4], const unsigned a[4],
                                        const unsigned b0, const unsigned b1,
                                        const float c[4]) {
    asm volatile(
        "mma.sync.aligned.m16n8k16.row.col.f32.f16.f16.f32 "
        "{%0,%1,%2,%3}, {%4,%5,%6,%7}, {%8,%9}, {%10,%11,%12,%13};"
        : "=f"(d[0]), "=f"(d[1]), "=f"(d[2]), "=f"(d[3])
        : "r"(a[0]), "r"(a[1]), "r"(a[2]), "r"(a[3]),
          "r"(b0), "r"(b1),
          "f"(c[0]), "f"(c[1]), "f"(c[2]), "f"(c[3]));
}

// ---------------------------------------------------------------------------
// fp16 GEMM: C[M,N] = A@W (+bias) (+res), fp32 in/out, fp32 accumulate.
// Block tile 64x128, BK=32, 256 threads (8 warps 2x4), warp tile 32x32.
// mma.m16n8k16. Words pack 2 fp16 along K.
//   As[64][20] words (16 + pad4):  frag bank = (20*gr+gc)%32  -> distinct
//   Bs[16][136] words:             frag bank = (8*gc+gr)%32   -> distinct
// ---------------------------------------------------------------------------
__device__ __forceinline__ void gemm_core(
    const float* __restrict__ A, const float* __restrict__ W,
    const float* __restrict__ bias, const float* __restrict__ res,
    float* __restrict__ C, int M, int N, int K)
{
    __shared__ unsigned As[64 * 20];
    __shared__ unsigned Bs[16 * 136];

    const int tid  = threadIdx.x;
    const int lane = tid & 31;
    const int warp = tid >> 5;
    const int wm   = warp & 1;
    const int wn   = warp >> 1;
    const int gr   = lane >> 2;
    const int gc   = lane & 3;

    const int bm = blockIdx.y * 64;
    const int bn = blockIdx.x * 128;

    // A staging: row = tid>>2 (0..63), fp32 col base c8 = (tid&3)*8
    const int arow = tid >> 2;
    const int ac8  = (tid & 3) * 8;

    float acc[2][4][4] = {};

    for (int k0 = 0; k0 < K; k0 += 32) {
        // --- A tile 64x32 fp32 -> 64x16 words ---
        {
            const float* ap = A + (size_t)(bm + arow) * K + k0 + ac8;
            float4 v0 = *(const float4*)(ap);
            float4 v1 = *(const float4*)(ap + 4);
            *(uint4*)&As[arow * 20 + ac8 / 2] = make_uint4(
                h2pack(v0.x, v0.y), h2pack(v0.z, v0.w),
                h2pack(v1.x, v1.y), h2pack(v1.z, v1.w));
        }
        // --- B tile 32x128 fp32 -> 16x128 words (pack across 2 K-rows) ---
#pragma unroll
        for (int i = 0; i < 2; i++) {
            int u  = tid + i * 256;
            int j  = u >> 5;            // 0..15
            int n4 = (u & 31) * 4;
            const float* w0 = W + (size_t)(k0 + 2 * j) * N + bn + n4;
            float4 a4 = *(const float4*)(w0);
            float4 b4 = *(const float4*)(w0 + N);
            *(uint4*)&Bs[j * 136 + n4] = make_uint4(
                h2pack(a4.x, b4.x), h2pack(a4.y, b4.y),
                h2pack(a4.z, b4.z), h2pack(a4.w, b4.w));
        }
        __syncthreads();

#pragma unroll
        for (int kk = 0; kk < 2; kk++) {            // two k16 chunks
            unsigned a[2][4], b[4][2];
#pragma unroll
            for (int mt = 0; mt < 2; mt++) {
                int row = wm * 32 + mt * 16 + gr;
                int j   = kk * 8 + gc;
                a[mt][0] = As[row * 20 + j];
                a[mt][1] = As[(row + 8) * 20 + j];
                a[mt][2] = As[row * 20 + j + 4];
                a[mt][3] = As[(row + 8) * 20 + j + 4];
            }
#pragma unroll
            for (int nt = 0; nt < 4; nt++) {
                int bc = wn * 32 + nt * 8 + gr;
                int j  = kk * 8 + gc;
                b[nt][0] = Bs[j * 136 + bc];
                b[nt][1] = Bs[(j + 4) * 136 + bc];
            }
#pragma unroll
            for (int mt = 0; mt < 2; mt++)
#pragma unroll
                for (int nt = 0; nt < 4; nt++)
                    mma_f16(acc[mt][nt], a[mt], b[nt][0], b[nt][1], acc[mt][nt]);
        }
        __syncthreads();
    }

    // Epilogue (fp32)
#pragma unroll
    for (int mt = 0; mt < 2; mt++) {
#pragma unroll
        for (int nt = 0; nt < 4; nt++) {
            int r0  = bm + wm * 32 + mt * 16 + gr;
            int col = bn + wn * 32 + nt * 8 + 2 * gc;
            float v0 = acc[mt][nt][0];
            float v1 = acc[mt][nt][1];
            float v2 = acc[mt][nt][2];
            float v3 = acc[mt][nt][3];
            if (bias) {
                float b0 = bias[col], b1 = bias[col + 1];
                v0 += b0; v1 += b1; v2 += b0; v3 += b1;
            }
            if (res) {
                float2 r0v = *(const float2*)(res + (size_t)r0 * N + col);
                float2 r1v = *(const float2*)(res + (size_t)(r0 + 8) * N + col);
                v0 += r0v.x; v1 += r0v.y; v2 += r1v.x; v3 += r1v.y;
            }
            *(float2*)(C + (size_t)r0 * N + col)       = make_float2(v0, v1);
            *(float2*)(C + (size_t)(r0 + 8) * N + col) = make_float2(v2, v3);
        }
    }
}

__global__ __launch_bounds__(256) void gemm_one(
    const float* __restrict__ A, const float* __restrict__ W,
    const float* __restrict__ bias, const float* __restrict__ res,
    float* __restrict__ C, int M, int N, int K)
{
    gemm_core(A, W, bias, res, C, M, N, K);
}

__global__ __launch_bounds__(256) void gemm_qkv(
    const float* __restrict__ Q, const float* __restrict__ K_,
    const float* __restrict__ V,
    const float* __restrict__ Wq, const float* __restrict__ Wk,
    const float* __restrict__ Wv,
    float* __restrict__ gq, float* __restrict__ gk, float* __restrict__ gv,
    int M, int N, int K)
{
    int z = blockIdx.z;
    const float* A = (z == 0) ? Q : (z == 1) ? K_ : V;
    const float* W = (z == 0) ? Wq : (z == 1) ? Wk : Wv;
    float* C       = (z == 0) ? gq : (z == 1) ? gk : gv;
    gemm_core(A, W, nullptr, nullptr, C, M, N, K);
}

// ---------------------------------------------------------------------------
// fp16 tensor-core flash attention over reinterpreted [16, 2048, 64].
// 128 queries/block, 8 warps (16 q-rows each), 64-key tiles, no-max softmax.
// P fragments built DIRECTLY in registers from exp(S-fragments) — no staging.
//   Qs[128][36] words: row-major K-pair words. frag bank (4gr+gc) distinct.
//   Ks[64][36]  words: same layout (B of S = K rows along K-dim).
//   Vs[32][68]  words: word(j,n) = {V[2j][n], V[2j+1][n]}.
// ---------------------------------------------------------------------------
__global__ __launch_bounds__(256) void attn_tc(
    const float* __restrict__ qp, const float* __restrict__ kp,
    const float* __restrict__ vp, float* __restrict__ op)
{
    __shared__ unsigned Qs[128 * 36];
    __shared__ unsigned Ks[64 * 36];
    __shared__ unsigned Vs[32 * 68];

    const int tid  = threadIdx.x;
    const int lane = tid & 31;
    const int warp = tid >> 5;
    const int gr   = lane >> 2;
    const int gc   = lane & 3;
    const int g    = blockIdx.y;
    const int q0   = blockIdx.x * 128;
    const float scale = 0.04419417382415922f;  // 1/sqrt(512)

    // Stage Q (scaled): 128 rows x 32 words = 1024 uint4, 4 per thread
    const float* qg = qp + ((size_t)g * 2048 + q0) * 64;
#pragma unroll
    for (int i = 0; i < 4; i++) {
        int u   = tid + i * 256;
        int row = u >> 3;
        int w8  = (u & 7) * 4;          // word offset 0,4,...,28
        const float* src = qg + (size_t)row * 64 + w8 * 2;
        float4 v0 = *(const float4*)(src);
        float4 v1 = *(const float4*)(src + 4);
        *(uint4*)&Qs[row * 36 + w8] = make_uint4(
            h2pack(v0.x * scale, v0.y * scale), h2pack(v0.z * scale, v0.w * scale),
            h2pack(v1.x * scale, v1.y * scale), h2pack(v1.z * scale, v1.w * scale));
    }
    __syncthreads();

    // Q fragments into registers: 4 k16-chunks
    unsigned qa[4][4];
    const int r = warp * 16 + gr;
#pragma unroll
    for (int kk = 0; kk < 4; kk++) {
        int j = kk * 8 + gc;
        qa[kk][0] = Qs[r * 36 + j];
        qa[kk][1] = Qs[(r + 8) * 36 + j];
        qa[kk][2] = Qs[r * 36 + j + 4];
        qa[kk][3] = Qs[(r + 8) * 36 + j + 4];
    }

    float oacc[8][4];
#pragma unroll
    for (int nt = 0; nt < 8; nt++)
#pragma unroll
        for (int i = 0; i < 4; i++) oacc[nt][i] = 0.f;
    float psum0 = 0.f, psum1 = 0.f;

    for (int kt = 0; kt < 32; kt++) {
        __syncthreads();
        const float* kg = kp + ((size_t)g * 2048 + kt * 64) * 64;
        const float* vg = vp + ((size_t)g * 2048 + kt * 64) * 64;
        // K: 64 rows x 32 words = 512 uint4, 2 per thread
#pragma unroll
        for (int i = 0; i < 2; i++) {
            int u   = tid + i * 256;
            int row = u >> 3;
            int w8  = (u & 7) * 4;
            const float* src = kg + (size_t)row * 64 + w8 * 2;
            float4 v0 = *(const float4*)(src);
            float4 v1 = *(const float4*)(src + 4);
            *(uint4*)&Ks[row * 36 + w8] = make_uint4(
                h2pack(v0.x, v0.y), h2pack(v0.z, v0.w),
                h2pack(v1.x, v1.y), h2pack(v1.z, v1.w));
        }
        // V: 32 j x 64 n words = 512 uint4, 2 per thread (pack across 2 rows)
#pragma unroll
        for (int i = 0; i < 2; i++) {
            int u  = tid + i * 256;
            int j  = u >> 4;            // 0..31
            int n4 = (u & 15) * 4;
            const float* v0p = vg + (size_t)(2 * j) * 64 + n4;
            float4 a4 = *(const float4*)(v0p);
            float4 b4 = *(const float4*)(v0p + 64);
            *(uint4*)&Vs[j * 68 + n4] = make_uint4(
                h2pack(a4.x, b4.x), h2pack(a4.y, b4.y),
                h2pack(a4.z, b4.z), h2pack(a4.w, b4.w));
        }
        __syncthreads();

        // S = Q @ K^T : 16 x 64 per warp (4 k16-chunks x 8 n-tiles)
        float sacc[8][4];
#pragma unroll
        for (int nt = 0; nt < 8; nt++)
#pragma unroll
            for (int i = 0; i < 4; i++) sacc[nt][i] = 0.f;
#pragma unroll
        for (int kk = 0; kk < 4; kk++) {
            int j = kk * 8 + gc;
#pragma unroll
            for (int nt = 0; nt < 8; nt++) {
                int key = nt * 8 + gr;
                mma_f16(sacc[nt], qa[kk], Ks[key * 36 + j], Ks[key * 36 + j + 4],
                        sacc[nt]);
            }
        }

        // P = exp(S) straight into fp16 A-fragments (no smem staging).
        // For P@V chunk kk: pa0={P[r][16kk+2gc..+1]} = sacc[2kk].{c0,c1}, etc.
        unsigned pa[4][4];
#pragma unroll
        for (int nt = 0; nt < 8; nt++) {
            float p0 = __expf(sacc[nt][0]);
            float p1 = __expf(sacc[nt][1]);
            float p2 = __expf(sacc[nt][2]);
            float p3 = __expf(sacc[nt][3]);
            psum0 += p0 + p1;
            psum1 += p2 + p3;
            int kk = nt >> 1;
            int hi = nt & 1;            // 0: keys +0..7 -> a0/a1, 1: +8..15 -> a2/a3
            pa[kk][hi * 2 + 0] = h2pack(p0, p1);
            pa[kk][hi * 2 + 1] = h2pack(p2, p3);
        }

        // O += P @ V : 4 k16-chunks x 8 n-tiles
#pragma unroll
        for (int kk = 0; kk < 4; kk++) {
            int j = kk * 8 + gc;
#pragma unroll
            for (int nt = 0; nt < 8; nt++) {
                int n = nt * 8 + gr;
                mma_f16(oacc[nt], pa[kk], Vs[j * 68 + n], Vs[(j + 4) * 68 + n],
                        oacc[nt]);
            }
        }
    }

    // Reduce denominators across the quad and write out
#pragma unroll
    for (int off = 1; off < 4; off <<= 1) {
        psum0 += __shfl_xor_sync(0xffffffffu, psum0, off);
        psum1 += __shfl_xor_sync(0xffffffffu, psum1, off);
    }
    float inv0 = 1.f / psum0;
    float inv1 = 1.f / psum1;
    int rr = q0 + warp * 16 + gr;
    float* og = op + ((size_t)g * 2048 + rr) * 64;
#pragma unroll
    for (int nt = 0; nt < 8; nt++) {
        *(float2*)(og + nt * 8 + 2 * gc) =
            make_float2(oacc[nt][0] * inv0, oacc[nt][1] * inv0);
        *(float2*)(og + 8 * 64 + nt * 8 + 2 * gc) =
            make_float2(oacc[nt][2] * inv1, oacc[nt][3] * inv1);
    }
}

// ---------------------------------------------------------------------------
// Vectorized in-place layernorm: 128 threads/row, float4 per thread.
// ---------------------------------------------------------------------------
__global__ __launch_bounds__(128) void ln512v(
    float* __restrict__ x, const float* __restrict__ gamma,
    const float* __restrict__ beta)
{
    const int row = blockIdx.x;
    const int tid = threadIdx.x;
    float4* p = (float4*)(x + (size_t)row * 512);
    float4 v = p[tid];
    float s  = v.x + v.y + v.z + v.w;
    float sq = v.x * v.x + v.y * v.y + v.z * v.z + v.w * v.w;
#pragma unroll
    for (int off = 16; off > 0; off >>= 1) {
        s  += __shfl_xor_sync(0xffffffffu, s, off);
        sq += __shfl_xor_sync(0xffffffffu, sq, off);
    }
    __shared__ float ws[4], wq[4];
    __shared__ float stats[2];
    if ((tid & 31) == 0) { ws[tid >> 5] = s; wq[tid >> 5] = sq; }
    __syncthreads();
    if (tid == 0) {
        float S = ws[0] + ws[1] + ws[2] + ws[3];
        float SQ = wq[0] + wq[1] + wq[2] + wq[3];
        float mu  = S * (1.f / 512.f);
        float var = SQ * (1.f / 512.f) - mu * mu;
        stats[0] = mu;
        stats[1] = rsqrtf(var + 1e-5f);
    }
    __syncthreads();
    float mu = stats[0], inv = stats[1];
    float4 gv = ((const float4*)gamma)[tid];
    float4 bv = ((const float4*)beta)[tid];
    p[tid] = make_float4((v.x - mu) * inv * gv.x + bv.x,
                         (v.y - mu) * inv * gv.y + bv.y,
                         (v.z - mu) * inv * gv.z + bv.z,
                         (v.w - mu) * inv * gv.w + bv.w);
}

// ---------------------------------------------------------------------------
extern "C" void kernel_launch(void* const* d_in, const int* in_sizes, int n_in,
                              void* d_out, int out_size)
{
    (void)in_sizes; (void)n_in; (void)out_size;
    const float* Q     = (const float*)d_in[0];
    const float* K     = (const float*)d_in[1];
    const float* V     = (const float*)d_in[2];
    const float* Wq    = (const float*)d_in[4];
    const float* Wk    = (const float*)d_in[5];
    const float* Wv    = (const float*)d_in[6];
    const float* Wo    = (const float*)d_in[7];
    const float* bo    = (const float*)d_in[8];
    const float* gamma = (const float*)d_in[9];
    const float* beta  = (const float*)d_in[10];
    const float* W1    = (const float*)d_in[11];
    const float* b1    = (const float*)d_in[12];
    const float* W2    = (const float*)d_in[13];
    const float* b2    = (const float*)d_in[14];
    float* out = (float*)d_out;

    float* base = nullptr;
    cudaGetSymbolAddress((void**)&base, g_scratch);
    float* gq    = base;
    float* gk    = base + (size_t)NQ;
    float* gv    = base + (size_t)2 * NQ;
    float* gattn = base + (size_t)3 * NQ;
    float* gZ    = base + (size_t)4 * NQ;
    float* gff   = base + (size_t)5 * NQ;

    // QKV projections (fused, 768 blocks of 64x128)
    gemm_qkv<<<dim3(D_MODEL / 128, M_ROWS / 64, 3), 256>>>(
        Q, K, V, Wq, Wk, Wv, gq, gk, gv, M_ROWS, D_MODEL, D_MODEL);

    // Tensor-core fp16 attention over reinterpreted [16, 2048, 64]
    attn_tc<<<dim3(16, 16), 256>>>(gq, gk, gv, gattn);

    // Output projection + bias + residual (X = V), then LN -> Z
    gemm_one<<<dim3(D_MODEL / 128, M_ROWS / 64), 256>>>(
        gattn, Wo, bo, V, gZ, M_ROWS, D_MODEL, D_MODEL);
    ln512v<<<M_ROWS, 128>>>(gZ, gamma, beta);

    // FFN (no activation in the reference)
    gemm_one<<<dim3(FF_DIM / 128, M_ROWS / 64), 256>>>(
        gZ, W1, b1, nullptr, gff, M_ROWS, FF_DIM, D_MODEL);
    gemm_one<<<dim3(D_MODEL / 128, M_ROWS / 64), 256>>>(
        gff, W2, b2, gZ, out, M_ROWS, D_MODEL, FF_DIM);
    ln512v<<<M_ROWS, 128>>>(out, gamma, beta);
}

// round 10
// speedup vs baseline: 1.5853x; 1.0143x over previous
#include <cuda_runtime.h>
#include <cuda_fp16.h>

#define M_ROWS 4096
#define D_MODEL 512
#define FF_DIM 2048
#define GELEMS (M_ROWS * D_MODEL)          // 2M elements per [B,S,D] buffer

__device__ __align__(16) float g_scratch[18 * 1024 * 1024];   // 72 MB

// ---------------------------------------------------------------------------
// fp16 helpers
// ---------------------------------------------------------------------------
__device__ __forceinline__ unsigned h2pack(float lo, float hi) {
    __half2 h = __floats2half2_rn(lo, hi);   // .x = lo half (low bytes)
    return *(unsigned*)&h;
}

__device__ __forceinline__ void mma_f16(float d[4], const unsigned a[4],
                                        const unsigned b0, const unsigned b1,
                                        const float c[4]) {
    asm volatile(
        "mma.sync.aligned.m16n8k16.row.col.f32.f16.f16.f32 "
        "{%0,%1,%2,%3}, {%4,%5,%6,%7}, {%8,%9}, {%10,%11,%12,%13};"
        : "=f"(d[0]), "=f"(d[1]), "=f"(d[2]), "=f"(d[3])
        : "r"(a[0]), "r"(a[1]), "r"(a[2]), "r"(a[3]),
          "r"(b0), "r"(b1),
          "f"(c[0]), "f"(c[1]), "f"(c[2]), "f"(c[3]));
}

// ---------------------------------------------------------------------------
// Pre-pass: fp32 -> fp16 elementwise (8 elems/thread)
// ---------------------------------------------------------------------------
__global__ __launch_bounds__(256) void cvt16(
    const float* __restrict__ in, __half* __restrict__ out, int n8)
{
    int i = blockIdx.x * 256 + threadIdx.x;
    if (i >= n8) return;
    const float4* p = (const float4*)in + 2 * (size_t)i;
    float4 a = p[0], b = p[1];
    ((uint4*)out)[i] = make_uint4(h2pack(a.x, a.y), h2pack(a.z, a.w),
                                  h2pack(b.x, b.y), h2pack(b.z, b.w));
}

// ---------------------------------------------------------------------------
// Pre-pass: fp32 W[K,N] -> fp16 Wt[N,K] (transpose), 32x32 smem tiles
// ---------------------------------------------------------------------------
__global__ __launch_bounds__(256) void cvtT(
    const float* __restrict__ W, __half* __restrict__ Wt, int K, int N)
{
    __shared__ float t[32][33];
    int n0 = blockIdx.x * 32, k0 = blockIdx.y * 32;
    int tx = threadIdx.x & 31, ty = threadIdx.x >> 5;   // ty 0..7
#pragma unroll
    for (int i = 0; i < 4; i++)
        t[ty + i * 8][tx] = W[(size_t)(k0 + ty + i * 8) * N + n0 + tx];
    __syncthreads();
#pragma unroll
    for (int i = 0; i < 4; i++)
        Wt[(size_t)(n0 + ty + i * 8) * K + k0 + tx] =
            __float2half(t[tx][ty + i * 8]);
}

// ---------------------------------------------------------------------------
// fp16-native GEMM: C[M,N] = A[M,K] @ Wt[N,K]^T, fp32 accumulate.
// Block 64x128, BK=32, 256 threads (8 warps 2x4), warp tile 32x32.
// Staging = raw uint4 copies (A and Wt already fp16, Wt pre-transposed).
//   As[64][20] words (16+pad4), Bs[128][20] words: frag banks distinct/quad.
// HOUT: fp16 output (optional bias, scale). !HOUT: fp32 output (+bias,+res).
// ---------------------------------------------------------------------------
template <bool HOUT>
__device__ __forceinline__ void gemm_core_h(
    const __half* __restrict__ A, const __half* __restrict__ Wt,
    const float* __restrict__ bias, const float* __restrict__ res,
    void* __restrict__ Cout, int M, int N, int K, float oscale)
{
    __shared__ unsigned As[64 * 20];
    __shared__ unsigned Bs[128 * 20];

    const int tid  = threadIdx.x;
    const int lane = tid & 31;
    const int warp = tid >> 5;
    const int wm   = warp & 1;
    const int wn   = warp >> 1;
    const int gr   = lane >> 2;
    const int gc   = lane & 3;

    const int bm = blockIdx.y * 64;
    const int bn = blockIdx.x * 128;

    const int arow = tid >> 2;
    const int ac4  = (tid & 3) * 4;     // word chunk within row

    float acc[2][4][4] = {};

    for (int k0 = 0; k0 < K; k0 += 32) {
        // A tile 64 rows x 16 words: 1 uint4 per thread
        *(uint4*)&As[arow * 20 + ac4] =
            *(const uint4*)(A + (size_t)(bm + arow) * K + k0 + ac4 * 2);
        // B tile 128 rows x 16 words: 2 uint4 per thread
#pragma unroll
        for (int i = 0; i < 2; i++) {
            int u = tid + i * 256;
            int br = u >> 2, bc4 = (u & 3) * 4;
            *(uint4*)&Bs[br * 20 + bc4] =
                *(const uint4*)(Wt + (size_t)(bn + br) * K + k0 + bc4 * 2);
        }
        __syncthreads();

#pragma unroll
        for (int kk = 0; kk < 2; kk++) {
            unsigned a[2][4], b[4][2];
            int j = kk * 8 + gc;
#pragma unroll
            for (int mt = 0; mt < 2; mt++) {
                int row = wm * 32 + mt * 16 + gr;
                a[mt][0] = As[row * 20 + j];
                a[mt][1] = As[(row + 8) * 20 + j];
                a[mt][2] = As[row * 20 + j + 4];
                a[mt][3] = As[(row + 8) * 20 + j + 4];
            }
#pragma unroll
            for (int nt = 0; nt < 4; nt++) {
                int bc = wn * 32 + nt * 8 + gr;
                b[nt][0] = Bs[bc * 20 + j];
                b[nt][1] = Bs[bc * 20 + j + 4];
            }
#pragma unroll
            for (int mt = 0; mt < 2; mt++)
#pragma unroll
                for (int nt = 0; nt < 4; nt++)
                    mma_f16(acc[mt][nt], a[mt], b[nt][0], b[nt][1], acc[mt][nt]);
        }
        __syncthreads();
    }

#pragma unroll
    for (int mt = 0; mt < 2; mt++) {
#pragma unroll
        for (int nt = 0; nt < 4; nt++) {
            int r0  = bm + wm * 32 + mt * 16 + gr;
            int col = bn + wn * 32 + nt * 8 + 2 * gc;
            float v0 = acc[mt][nt][0] * oscale;
            float v1 = acc[mt][nt][1] * oscale;
            float v2 = acc[mt][nt][2] * oscale;
            float v3 = acc[mt][nt][3] * oscale;
            if (bias) {
                float b0 = bias[col], b1 = bias[col + 1];
                v0 += b0; v1 += b1; v2 += b0; v3 += b1;
            }
            if (HOUT) {
                __half* C = (__half*)Cout;
                *(unsigned*)(C + (size_t)r0 * N + col)       = h2pack(v0, v1);
                *(unsigned*)(C + (size_t)(r0 + 8) * N + col) = h2pack(v2, v3);
            } else {
                float* C = (float*)Cout;
                if (res) {
                    float2 r0v = *(const float2*)(res + (size_t)r0 * N + col);
                    float2 r1v = *(const float2*)(res + (size_t)(r0 + 8) * N + col);
                    v0 += r0v.x; v1 += r0v.y; v2 += r1v.x; v3 += r1v.y;
                }
                *(float2*)(C + (size_t)r0 * N + col)       = make_float2(v0, v1);
                *(float2*)(C + (size_t)(r0 + 8) * N + col) = make_float2(v2, v3);
            }
        }
    }
}

__global__ __launch_bounds__(256) void gemm_h2h(
    const __half* __restrict__ A, const __half* __restrict__ Wt,
    const float* __restrict__ bias, __half* __restrict__ C,
    int M, int N, int K, float sc)
{
    gemm_core_h<true>(A, Wt, bias, nullptr, C, M, N, K, sc);
}

__global__ __launch_bounds__(256) void gemm_h2f(
    const __half* __restrict__ A, const __half* __restrict__ Wt,
    const float* __restrict__ bias, const float* __restrict__ res,
    float* __restrict__ C, int M, int N, int K)
{
    gemm_core_h<false>(A, Wt, bias, res, C, M, N, K, 1.f);
}

__global__ __launch_bounds__(256) void gemm_qkvh(
    const __half* __restrict__ Qh, const __half* __restrict__ Kh,
    const __half* __restrict__ Vh,
    const __half* __restrict__ wqT, const __half* __restrict__ wkT,
    const __half* __restrict__ wvT,
    __half* __restrict__ gq, __half* __restrict__ gk, __half* __restrict__ gv,
    int M, int N, int K, float qscale)
{
    int z = blockIdx.z;
    const __half* A  = (z == 0) ? Qh : (z == 1) ? Kh : Vh;
    const __half* Wt = (z == 0) ? wqT : (z == 1) ? wkT : wvT;
    __half* C        = (z == 0) ? gq : (z == 1) ? gk : gv;
    float sc         = (z == 0) ? qscale : 1.f;
    gemm_core_h<true>(A, Wt, nullptr, nullptr, C, M, N, K, sc);
}

// ---------------------------------------------------------------------------
// fp16 flash attention over reinterpreted [16, 2048, 64]; fp16 in/out.
// Q pre-scaled by 1/sqrt(512) in the QKV GEMM epilogue. No-max softmax.
// Staging: Q/K raw uint4 copies; V interleaved across row pairs via PRMT.
// ---------------------------------------------------------------------------
__global__ __launch_bounds__(256) void attn_tc(
    const __half* __restrict__ qp, const __half* __restrict__ kp,
    const __half* __restrict__ vp, __half* __restrict__ op)
{
    __shared__ unsigned Qs[128 * 36];
    __shared__ unsigned Ks[64 * 36];
    __shared__ unsigned Vs[32 * 68];

    const int tid  = threadIdx.x;
    const int lane = tid & 31;
    const int warp = tid >> 5;
    const int gr   = lane >> 2;
    const int gc   = lane & 3;
    const int g    = blockIdx.y;
    const int q0   = blockIdx.x * 128;

    // Q: 128 rows x 32 words, raw copy (4 uint4 per thread)
    const __half* qg = qp + ((size_t)g * 2048 + q0) * 64;
#pragma unroll
    for (int i = 0; i < 4; i++) {
        int u = tid + i * 256;
        int row = u >> 3, wc = (u & 7) * 4;
        *(uint4*)&Qs[row * 36 + wc] =
            *(const uint4*)(qg + (size_t)row * 64 + wc * 2);
    }
    __syncthreads();

    unsigned qa[4][4];
    const int r = warp * 16 + gr;
#pragma unroll
    for (int kk = 0; kk < 4; kk++) {
        int j = kk * 8 + gc;
        qa[kk][0] = Qs[r * 36 + j];
        qa[kk][1] = Qs[(r + 8) * 36 + j];
        qa[kk][2] = Qs[r * 36 + j + 4];
        qa[kk][3] = Qs[(r + 8) * 36 + j + 4];
    }

    float oacc[8][4];
#pragma unroll
    for (int nt = 0; nt < 8; nt++)
#pragma unroll
        for (int i = 0; i < 4; i++) oacc[nt][i] = 0.f;
    float psum0 = 0.f, psum1 = 0.f;

    for (int kt = 0; kt < 32; kt++) {
        __syncthreads();
        const __half* kg = kp + ((size_t)g * 2048 + kt * 64) * 64;
        const __half* vg = vp + ((size_t)g * 2048 + kt * 64) * 64;
        // K: 64 rows x 32 words, raw copy
#pragma unroll
        for (int i = 0; i < 2; i++) {
            int u = tid + i * 256;
            int row = u >> 3, wc = (u & 7) * 4;
            *(uint4*)&Ks[row * 36 + wc] =
                *(const uint4*)(kg + (size_t)row * 64 + wc * 2);
        }
        // V: word(j,n) = {V[2j][n], V[2j+1][n]} via byte_perm
#pragma unroll
        for (int i = 0; i < 2; i++) {
            int u = tid + i * 256;
            int j = u >> 4, n0 = (u & 15) * 4;
            uint2 r0 = *(const uint2*)(vg + (size_t)(2 * j) * 64 + n0);
            uint2 r1 = *(const uint2*)(vg + (size_t)(2 * j + 1) * 64 + n0);
            *(uint4*)&Vs[j * 68 + n0] = make_uint4(
                __byte_perm(r0.x, r1.x, 0x5410), __byte_perm(r0.x, r1.x, 0x7632),
                __byte_perm(r0.y, r1.y, 0x5410), __byte_perm(r0.y, r1.y, 0x7632));
        }
        __syncthreads();

        // S = Q @ K^T
        float sacc[8][4];
#pragma unroll
        for (int nt = 0; nt < 8; nt++)
#pragma unroll
            for (int i = 0; i < 4; i++) sacc[nt][i] = 0.f;
#pragma unroll
        for (int kk = 0; kk < 4; kk++) {
            int j = kk * 8 + gc;
#pragma unroll
            for (int nt = 0; nt < 8; nt++) {
                int key = nt * 8 + gr;
                mma_f16(sacc[nt], qa[kk], Ks[key * 36 + j], Ks[key * 36 + j + 4],
                        sacc[nt]);
            }
        }

        // P = exp(S) straight into fp16 A-fragments
        unsigned pa[4][4];
#pragma unroll
        for (int nt = 0; nt < 8; nt++) {
            float p0 = __expf(sacc[nt][0]);
            float p1 = __expf(sacc[nt][1]);
            float p2 = __expf(sacc[nt][2]);
            float p3 = __expf(sacc[nt][3]);
            psum0 += p0 + p1;
            psum1 += p2 + p3;
            int kk = nt >> 1;
            int hi = nt & 1;
            pa[kk][hi * 2 + 0] = h2pack(p0, p1);
            pa[kk][hi * 2 + 1] = h2pack(p2, p3);
        }

        // O += P @ V
#pragma unroll
        for (int kk = 0; kk < 4; kk++) {
            int j = kk * 8 + gc;
#pragma unroll
            for (int nt = 0; nt < 8; nt++) {
                int n = nt * 8 + gr;
                mma_f16(oacc[nt], pa[kk], Vs[j * 68 + n], Vs[(j + 4) * 68 + n],
                        oacc[nt]);
            }
        }
    }

#pragma unroll
    for (int off = 1; off < 4; off <<= 1) {
        psum0 += __shfl_xor_sync(0xffffffffu, psum0, off);
        psum1 += __shfl_xor_sync(0xffffffffu, psum1, off);
    }
    float inv0 = 1.f / psum0;
    float inv1 = 1.f / psum1;
    int rr = q0 + warp * 16 + gr;
    unsigned* og = (unsigned*)(op + ((size_t)g * 2048 + rr) * 64);
#pragma unroll
    for (int nt = 0; nt < 8; nt++) {
        og[nt * 4 + gc]          = h2pack(oacc[nt][0] * inv0, oacc[nt][1] * inv0);
        og[8 * 32 + nt * 4 + gc] = h2pack(oacc[nt][2] * inv1, oacc[nt][3] * inv1);
    }
}

// ---------------------------------------------------------------------------
// Layernorm (fp32 in-place, optional fp16 copy out). 128 thr/row, float4.
// ---------------------------------------------------------------------------
__global__ __launch_bounds__(128) void ln512v(
    float* __restrict__ x, const float* __restrict__ gamma,
    const float* __restrict__ beta, __half* __restrict__ xc)
{
    const int row = blockIdx.x;
    const int tid = threadIdx.x;
    float4* p = (float4*)(x + (size_t)row * 512);
    float4 v = p[tid];
    float s  = v.x + v.y + v.z + v.w;
    float sq = v.x * v.x + v.y * v.y + v.z * v.z + v.w * v.w;
#pragma unroll
    for (int off = 16; off > 0; off >>= 1) {
        s  += __shfl_xor_sync(0xffffffffu, s, off);
        sq += __shfl_xor_sync(0xffffffffu, sq, off);
    }
    __shared__ float ws[4], wq[4];
    __shared__ float stats[2];
    if ((tid & 31) == 0) { ws[tid >> 5] = s; wq[tid >> 5] = sq; }
    __syncthreads();
    if (tid == 0) {
        float S  = ws[0] + ws[1] + ws[2] + ws[3];
        float SQ = wq[0] + wq[1] + wq[2] + wq[3];
        float mu  = S * (1.f / 512.f);
        float var = SQ * (1.f / 512.f) - mu * mu;
        stats[0] = mu;
        stats[1] = rsqrtf(var + 1e-5f);
    }
    __syncthreads();
    float mu = stats[0], inv = stats[1];
    float4 gv = ((const float4*)gamma)[tid];
    float4 bv = ((const float4*)beta)[tid];
    float4 o = make_float4((v.x - mu) * inv * gv.x + bv.x,
                           (v.y - mu) * inv * gv.y + bv.y,
                           (v.z - mu) * inv * gv.z + bv.z,
                           (v.w - mu) * inv * gv.w + bv.w);
    p[tid] = o;
    if (xc) {
        ((uint2*)(xc + (size_t)row * 512))[tid] =
            make_uint2(h2pack(o.x, o.y), h2pack(o.z, o.w));
    }
}

// ---------------------------------------------------------------------------
extern "C" void kernel_launch(void* const* d_in, const int* in_sizes, int n_in,
                              void* d_out, int out_size)
{
    (void)in_sizes; (void)n_in; (void)out_size;
    const float* Q     = (const float*)d_in[0];
    const float* K     = (const float*)d_in[1];
    const float* V     = (const float*)d_in[2];
    const float* Wq    = (const float*)d_in[4];
    const float* Wk    = (const float*)d_in[5];
    const float* Wv    = (const float*)d_in[6];
    const float* Wo    = (const float*)d_in[7];
    const float* bo    = (const float*)d_in[8];
    const float* gamma = (const float*)d_in[9];
    const float* beta  = (const float*)d_in[10];
    const float* W1    = (const float*)d_in[11];
    const float* b1    = (const float*)d_in[12];
    const float* W2    = (const float*)d_in[13];
    const float* b2    = (const float*)d_in[14];
    float* out = (float*)d_out;

    char* base = nullptr;
    cudaGetSymbolAddress((void**)&base, g_scratch);
    const size_t MB = 1024 * 1024;
    __half* qh    = (__half*)(base);                 // 4 MB
    __half* kh    = (__half*)(base + 4  * MB);       // 4 MB
    __half* vh    = (__half*)(base + 8  * MB);       // 4 MB
    __half* wqT   = (__half*)(base + 12 * MB);       // 0.5 MB
    __half* wkT   = (__half*)(base + 13 * MB);       // 0.5 MB
    __half* wvT   = (__half*)(base + 14 * MB);       // 0.5 MB
    __half* woT   = (__half*)(base + 15 * MB);       // 0.5 MB
    __half* w1T   = (__half*)(base + 16 * MB);       // 2 MB
    __half* w2T   = (__half*)(base + 18 * MB);       // 2 MB
    __half* gq    = (__half*)(base + 20 * MB);       // 4 MB
    __half* gk    = (__half*)(base + 24 * MB);       // 4 MB
    __half* gv    = (__half*)(base + 28 * MB);       // 4 MB
    __half* gattn = (__half*)(base + 32 * MB);       // 4 MB
    float*  gZ    = (float*) (base + 36 * MB);       // 8 MB
    __half* gZc   = (__half*)(base + 44 * MB);       // 4 MB
    __half* gff   = (__half*)(base + 48 * MB);       // 16 MB

    const float qscale = 0.04419417382415922f;       // 1/sqrt(512)

    // ---- pre-pass: fp16 conversions + weight transposes ----
    cvt16<<<GELEMS / (256 * 8), 256>>>(Q, qh, GELEMS / 8);
    cvt16<<<GELEMS / (256 * 8), 256>>>(K, kh, GELEMS / 8);
    cvt16<<<GELEMS / (256 * 8), 256>>>(V, vh, GELEMS / 8);
    cvtT<<<dim3(512 / 32, 512 / 32), 256>>>(Wq, wqT, 512, 512);
    cvtT<<<dim3(512 / 32, 512 / 32), 256>>>(Wk, wkT, 512, 512);
    cvtT<<<dim3(512 / 32, 512 / 32), 256>>>(Wv, wvT, 512, 512);
    cvtT<<<dim3(512 / 32, 512 / 32), 256>>>(Wo, woT, 512, 512);
    cvtT<<<dim3(2048 / 32, 512 / 32), 256>>>(W1, w1T, 512, 2048);
    cvtT<<<dim3(512 / 32, 2048 / 32), 256>>>(W2, w2T, 2048, 512);

    // ---- QKV projections (gq pre-scaled by 1/sqrt(512)) ----
    gemm_qkvh<<<dim3(D_MODEL / 128, M_ROWS / 64, 3), 256>>>(
        qh, kh, vh, wqT, wkT, wvT, gq, gk, gv, M_ROWS, D_MODEL, D_MODEL, qscale);

    // ---- attention over reinterpreted [16, 2048, 64], fp16 ----
    attn_tc<<<dim3(16, 16), 256>>>(gq, gk, gv, gattn);

    // ---- Wo projection + bias + residual(V fp32) -> gZ fp32, then LN ----
    gemm_h2f<<<dim3(D_MODEL / 128, M_ROWS / 64), 256>>>(
        gattn, woT, bo, V, gZ, M_ROWS, D_MODEL, D_MODEL);
    ln512v<<<M_ROWS, 128>>>(gZ, gamma, beta, gZc);

    // ---- FFN ----
    gemm_h2h<<<dim3(FF_DIM / 128, M_ROWS / 64), 256>>>(
        gZc, w1T, b1, gff, M_ROWS, FF_DIM, D_MODEL, 1.f);
    gemm_h2f<<<dim3(D_MODEL / 128, M_ROWS / 64), 256>>>(
        gff, w2T, b2, gZ, out, M_ROWS, D_MODEL, FF_DIM);
    ln512v<<<M_ROWS, 128>>>(out, gamma, beta, nullptr);
}

// round 11
// speedup vs baseline: 1.7861x; 1.1266x over previous
#include <cuda_runtime.h>
#include <cuda_fp16.h>

#define M_ROWS 4096
#define D_MODEL 512
#define FF_DIM 2048
#define GELEMS (M_ROWS * D_MODEL)

__device__ __align__(16) float g_scratch[18 * 1024 * 1024];   // 72 MB

// ---------------------------------------------------------------------------
// helpers
// ---------------------------------------------------------------------------
__device__ __forceinline__ unsigned h2pack(float lo, float hi) {
    __half2 h = __floats2half2_rn(lo, hi);
    return *(unsigned*)&h;
}

__device__ __forceinline__ unsigned ex2h2(unsigned x) {
    unsigned d;
    asm("ex2.approx.f16x2 %0, %1;" : "=r"(d) : "r"(x));
    return d;
}

__device__ __forceinline__ void mma_f16(float d[4], const unsigned a[4],
                                        const unsigned b0, const unsigned b1,
                                        const float c[4]) {
    asm volatile(
        "mma.sync.aligned.m16n8k16.row.col.f32.f16.f16.f32 "
        "{%0,%1,%2,%3}, {%4,%5,%6,%7}, {%8,%9}, {%10,%11,%12,%13};"
        : "=f"(d[0]), "=f"(d[1]), "=f"(d[2]), "=f"(d[3])
        : "r"(a[0]), "r"(a[1]), "r"(a[2]), "r"(a[3]),
          "r"(b0), "r"(b1),
          "f"(c[0]), "f"(c[1]), "f"(c[2]), "f"(c[3]));
}

#define LDSM_X4(r, addr) \
    asm volatile("ldmatrix.sync.aligned.m8n8.x4.shared.b16 {%0,%1,%2,%3}, [%4];" \
        : "=r"((r)[0]), "=r"((r)[1]), "=r"((r)[2]), "=r"((r)[3]) : "r"(addr))

__device__ __forceinline__ unsigned saddr(const void* p) {
    return (unsigned)__cvta_generic_to_shared(p);
}

// ---------------------------------------------------------------------------
// Pre-pass 1: Q,K,V fp32 -> fp16, one launch (z selects buffer)
// ---------------------------------------------------------------------------
__global__ __launch_bounds__(256) void cvt16_all(
    const float* __restrict__ Q, const float* __restrict__ K,
    const float* __restrict__ V,
    __half* __restrict__ qh, __half* __restrict__ kh, __half* __restrict__ vh)
{
    int z = blockIdx.z;
    const float* in = (z == 0) ? Q : (z == 1) ? K : V;
    __half* out     = (z == 0) ? qh : (z == 1) ? kh : vh;
    int i = blockIdx.x * 256 + threadIdx.x;          // < GELEMS/8
    const float4* p = (const float4*)in + 2 * (size_t)i;
    float4 a = p[0], b = p[1];
    ((uint4*)out)[i] = make_uint4(h2pack(a.x, a.y), h2pack(a.z, a.w),
                                  h2pack(b.x, b.y), h2pack(b.z, b.w));
}

// ---------------------------------------------------------------------------
// Pre-pass 2: all 6 weight transposes fp32[K,N] -> fp16[N,K], one launch.
// Flat block index: [0,1024) = Wq/Wk/Wv/Wo (256 tiles each),
// [1024,2048) = W1 (K=512,N=2048), [2048,3072) = W2 (K=2048,N=512).
// ---------------------------------------------------------------------------
__global__ __launch_bounds__(256) void cvtT_all(
    const float* __restrict__ Wq, const float* __restrict__ Wk,
    const float* __restrict__ Wv, const float* __restrict__ Wo,
    const float* __restrict__ W1, const float* __restrict__ W2,
    __half* __restrict__ wqT, __half* __restrict__ wkT,
    __half* __restrict__ wvT, __half* __restrict__ woT,
    __half* __restrict__ w1T, __half* __restrict__ w2T)
{
    __shared__ float t[32][33];
    int idx = blockIdx.x;
    const float* W; __half* Wt; int K, N, n0, k0;
    if (idx < 1024) {
        int w = idx >> 8, tt = idx & 255;
        K = 512; N = 512;
        W  = (w == 0) ? Wq : (w == 1) ? Wk : (w == 2) ? Wv : Wo;
        Wt = (w == 0) ? wqT : (w == 1) ? wkT : (w == 2) ? wvT : woT;
        n0 = (tt & 15) * 32; k0 = (tt >> 4) * 32;
    } else if (idx < 2048) {
        int tt = idx - 1024;
        K = 512; N = 2048; W = W1; Wt = w1T;
        n0 = (tt & 63) * 32; k0 = (tt >> 6) * 32;
    } else {
        int tt = idx - 2048;
        K = 2048; N = 512; W = W2; Wt = w2T;
        n0 = (tt & 15) * 32; k0 = (tt >> 4) * 32;
    }
    int tx = threadIdx.x & 31, ty = threadIdx.x >> 5;
#pragma unroll
    for (int i = 0; i < 4; i++)
        t[ty + i * 8][tx] = W[(size_t)(k0 + ty + i * 8) * N + n0 + tx];
    __syncthreads();
#pragma unroll
    for (int i = 0; i < 4; i++)
        Wt[(size_t)(n0 + ty + i * 8) * K + k0 + tx] =
            __float2half(t[tx][ty + i * 8]);
}

// ---------------------------------------------------------------------------
// fp16-native GEMM with ldmatrix fragments: C = A[M,K] @ Wt[N,K]^T.
// Block 64x128, BK=32, 256 threads, warp tile 32x32.
// ---------------------------------------------------------------------------
template <bool HOUT>
__device__ __forceinline__ void gemm_core_h(
    const __half* __restrict__ A, const __half* __restrict__ Wt,
    const float* __restrict__ bias, const float* __restrict__ res,
    void* __restrict__ Cout, int M, int N, int K, float oscale)
{
    __shared__ unsigned As[64 * 20];
    __shared__ unsigned Bs[128 * 20];

    const int tid  = threadIdx.x;
    const int lane = tid & 31;
    const int warp = tid >> 5;
    const int wm   = warp & 1;
    const int wn   = warp >> 1;
    const int gr   = lane >> 2;
    const int gc   = lane & 3;
    const int li   = lane & 7;
    const int seg  = lane >> 3;

    const int bm = blockIdx.y * 64;
    const int bn = blockIdx.x * 128;

    const int arow = tid >> 2;
    const int ac4  = (tid & 3) * 4;

    // ldmatrix lane base addresses (constant across K loop)
    const unsigned aBase =
        saddr(&As[(wm * 32 + li + (seg & 1) * 8) * 20 + (seg >> 1) * 4]);
    const unsigned bBase =
        saddr(&Bs[(wn * 32 + li + (seg >> 1) * 8) * 20 + (seg & 1) * 4]);

    float acc[2][4][4] = {};

    for (int k0 = 0; k0 < K; k0 += 32) {
        *(uint4*)&As[arow * 20 + ac4] =
            *(const uint4*)(A + (size_t)(bm + arow) * K + k0 + ac4 * 2);
#pragma unroll
        for (int i = 0; i < 2; i++) {
            int u = tid + i * 256;
            int br = u >> 2, bc4 = (u & 3) * 4;
            *(uint4*)&Bs[br * 20 + bc4] =
                *(const uint4*)(Wt + (size_t)(bn + br) * K + k0 + bc4 * 2);
        }
        __syncthreads();

#pragma unroll
        for (int kk = 0; kk < 2; kk++) {
            unsigned a0[4], a1[4], bb0[4], bb1[4];
            LDSM_X4(a0,  aBase + (kk * 8) * 4);
            LDSM_X4(a1,  aBase + (16 * 20 + kk * 8) * 4);
            LDSM_X4(bb0, bBase + (kk * 8) * 4);
            LDSM_X4(bb1, bBase + (16 * 20 + kk * 8) * 4);
            mma_f16(acc[0][0], a0, bb0[0], bb0[1], acc[0][0]);
            mma_f16(acc[0][1], a0, bb0[2], bb0[3], acc[0][1]);
            mma_f16(acc[0][2], a0, bb1[0], bb1[1], acc[0][2]);
            mma_f16(acc[0][3], a0, bb1[2], bb1[3], acc[0][3]);
            mma_f16(acc[1][0], a1, bb0[0], bb0[1], acc[1][0]);
            mma_f16(acc[1][1], a1, bb0[2], bb0[3], acc[1][1]);
            mma_f16(acc[1][2], a1, bb1[0], bb1[1], acc[1][2]);
            mma_f16(acc[1][3], a1, bb1[2], bb1[3], acc[1][3]);
        }
        __syncthreads();
    }

#pragma unroll
    for (int mt = 0; mt < 2; mt++) {
#pragma unroll
        for (int nt = 0; nt < 4; nt++) {
            int r0  = bm + wm * 32 + mt * 16 + gr;
            int col = bn + wn * 32 + nt * 8 + 2 * gc;
            float v0 = acc[mt][nt][0] * oscale;
            float v1 = acc[mt][nt][1] * oscale;
            float v2 = acc[mt][nt][2] * oscale;
            float v3 = acc[mt][nt][3] * oscale;
            if (bias) {
                float b0 = bias[col], b1 = bias[col + 1];
                v0 += b0; v1 += b1; v2 += b0; v3 += b1;
            }
            if (HOUT) {
                __half* C = (__half*)Cout;
                *(unsigned*)(C + (size_t)r0 * N + col)       = h2pack(v0, v1);
                *(unsigned*)(C + (size_t)(r0 + 8) * N + col) = h2pack(v2, v3);
            } else {
                float* C = (float*)Cout;
                if (res) {
                    float2 r0v = *(const float2*)(res + (size_t)r0 * N + col);
                    float2 r1v = *(const float2*)(res + (size_t)(r0 + 8) * N + col);
                    v0 += r0v.x; v1 += r0v.y; v2 += r1v.x; v3 += r1v.y;
                }
                *(float2*)(C + (size_t)r0 * N + col)       = make_float2(v0, v1);
                *(float2*)(C + (size_t)(r0 + 8) * N + col) = make_float2(v2, v3);
            }
        }
    }
}

__global__ __launch_bounds__(256) void gemm_h2h(
    const __half* __restrict__ A, const __half* __restrict__ Wt,
    const float* __restrict__ bias, __half* __restrict__ C,
    int M, int N, int K, float sc)
{
    gemm_core_h<true>(A, Wt, bias, nullptr, C, M, N, K, sc);
}

__global__ __launch_bounds__(256) void gemm_h2f(
    const __half* __restrict__ A, const __half* __restrict__ Wt,
    const float* __restrict__ bias, const float* __restrict__ res,
    float* __restrict__ C, int M, int N, int K)
{
    gemm_core_h<false>(A, Wt, bias, res, C, M, N, K, 1.f);
}

__global__ __launch_bounds__(256) void gemm_qkvh(
    const __half* __restrict__ Qh, const __half* __restrict__ Kh,
    const __half* __restrict__ Vh,
    const __half* __restrict__ wqT, const __half* __restrict__ wkT,
    const __half* __restrict__ wvT,
    __half* __restrict__ gq, __half* __restrict__ gk, __half* __restrict__ gv,
    int M, int N, int K, float qscale)
{
    int z = blockIdx.z;
    const __half* A  = (z == 0) ? Qh : (z == 1) ? Kh : Vh;
    const __half* Wt = (z == 0) ? wqT : (z == 1) ? wkT : wvT;
    __half* C        = (z == 0) ? gq : (z == 1) ? gk : gv;
    float sc         = (z == 0) ? qscale : 1.f;
    gemm_core_h<true>(A, Wt, nullptr, nullptr, C, M, N, K, sc);
}

// ---------------------------------------------------------------------------
// fp16 flash attention. Q pre-scaled by log2(e)/sqrt(512) -> P = 2^S via
// ex2.approx.f16x2. Softmax denominator via mma against all-ones B (exact
// row-sum on the tensor pipe, no shuffles). K fragments via ldmatrix.
// ---------------------------------------------------------------------------
__global__ __launch_bounds__(256) void attn_tc(
    const __half* __restrict__ qp, const __half* __restrict__ kp,
    const __half* __restrict__ vp, __half* __restrict__ op)
{
    __shared__ unsigned Qs[128 * 36];
    __shared__ unsigned Ks[64 * 36];
    __shared__ unsigned Vs[32 * 68];

    const int tid  = threadIdx.x;
    const int lane = tid & 31;
    const int warp = tid >> 5;
    const int gr   = lane >> 2;
    const int gc   = lane & 3;
    const int li   = lane & 7;
    const int seg  = lane >> 3;
    const int g    = blockIdx.y;
    const int q0   = blockIdx.x * 128;
    const unsigned ONES = 0x3C003C00u;   // {1.0h, 1.0h}

    const __half* qg = qp + ((size_t)g * 2048 + q0) * 64;
#pragma unroll
    for (int i = 0; i < 4; i++) {
        int u = tid + i * 256;
        int row = u >> 3, wc = (u & 7) * 4;
        *(uint4*)&Qs[row * 36 + wc] =
            *(const uint4*)(qg + (size_t)row * 64 + wc * 2);
    }
    __syncthreads();

    unsigned qa[4][4];
    const int r = warp * 16 + gr;
#pragma unroll
    for (int kk = 0; kk < 4; kk++) {
        int j = kk * 8 + gc;
        qa[kk][0] = Qs[r * 36 + j];
        qa[kk][1] = Qs[(r + 8) * 36 + j];
        qa[kk][2] = Qs[r * 36 + j + 4];
        qa[kk][3] = Qs[(r + 8) * 36 + j + 4];
    }

    // ldmatrix base for K fragments
    const unsigned kBase =
        saddr(&Ks[(li + (seg >> 1) * 8) * 36 + (seg & 1) * 4]);

    float oacc[8][4];
#pragma unroll
    for (int nt = 0; nt < 8; nt++)
#pragma unroll
        for (int i = 0; i < 4; i++) oacc[nt][i] = 0.f;
    float psacc[4] = {0.f, 0.f, 0.f, 0.f};

    for (int kt = 0; kt < 32; kt++) {
        __syncthreads();
        const __half* kg = kp + ((size_t)g * 2048 + kt * 64) * 64;
        const __half* vg = vp + ((size_t)g * 2048 + kt * 64) * 64;
#pragma unroll
        for (int i = 0; i < 2; i++) {
            int u = tid + i * 256;
            int row = u >> 3, wc = (u & 7) * 4;
            *(uint4*)&Ks[row * 36 + wc] =
                *(const uint4*)(kg + (size_t)row * 64 + wc * 2);
        }
#pragma unroll
        for (int i = 0; i < 2; i++) {
            int u = tid + i * 256;
            int j = u >> 4, n0 = (u & 15) * 4;
            uint2 r0 = *(const uint2*)(vg + (size_t)(2 * j) * 64 + n0);
            uint2 r1 = *(const uint2*)(vg + (size_t)(2 * j + 1) * 64 + n0);
            *(uint4*)&Vs[j * 68 + n0] = make_uint4(
                __byte_perm(r0.x, r1.x, 0x5410), __byte_perm(r0.x, r1.x, 0x7632),
                __byte_perm(r0.y, r1.y, 0x5410), __byte_perm(r0.y, r1.y, 0x7632));
        }
        __syncthreads();

        // S = Q @ K^T (K frags via ldmatrix)
        float sacc[8][4];
#pragma unroll
        for (int nt = 0; nt < 8; nt++)
#pragma unroll
            for (int i = 0; i < 4; i++) sacc[nt][i] = 0.f;
#pragma unroll
        for (int kk = 0; kk < 4; kk++) {
#pragma unroll
            for (int ntp = 0; ntp < 4; ntp++) {
                unsigned kb[4];
                LDSM_X4(kb, kBase + (ntp * 16 * 36 + kk * 8) * 4);
                mma_f16(sacc[2 * ntp],     qa[kk], kb[0], kb[1], sacc[2 * ntp]);
                mma_f16(sacc[2 * ntp + 1], qa[kk], kb[2], kb[3], sacc[2 * ntp + 1]);
            }
        }

        // P = 2^S  (fp16x2 ex2), packed directly into A-fragments
        unsigned pa[4][4];
#pragma unroll
        for (int nt = 0; nt < 8; nt++) {
            int kk = nt >> 1;
            int hi = nt & 1;
            pa[kk][hi * 2 + 0] = ex2h2(h2pack(sacc[nt][0], sacc[nt][1]));
            pa[kk][hi * 2 + 1] = ex2h2(h2pack(sacc[nt][2], sacc[nt][3]));
        }

        // O += P @ V ; denominator += P @ ones (exact row-sum via tensor core)
#pragma unroll
        for (int kk = 0; kk < 4; kk++) {
            int j = kk * 8 + gc;
#pragma unroll
            for (int nt = 0; nt < 8; nt++) {
                int n = nt * 8 + gr;
                mma_f16(oacc[nt], pa[kk], Vs[j * 68 + n], Vs[(j + 4) * 68 + n],
                        oacc[nt]);
            }
            mma_f16(psacc, pa[kk], ONES, ONES, psacc);
        }
    }

    float inv0 = 1.f / psacc[0];
    float inv1 = 1.f / psacc[2];
    int rr = q0 + warp * 16 + gr;
    unsigned* og = (unsigned*)(op + ((size_t)g * 2048 + rr) * 64);
#pragma unroll
    for (int nt = 0; nt < 8; nt++) {
        og[nt * 4 + gc]          = h2pack(oacc[nt][0] * inv0, oacc[nt][1] * inv0);
        og[8 * 32 + nt * 4 + gc] = h2pack(oacc[nt][2] * inv1, oacc[nt][3] * inv1);
    }
}

// ---------------------------------------------------------------------------
// Layernorm (fp32 in-place, optional fp16 copy out). 128 thr/row, float4.
// ---------------------------------------------------------------------------
__global__ __launch_bounds__(128) void ln512v(
    float* __restrict__ x, const float* __restrict__ gamma,
    const float* __restrict__ beta, __half* __restrict__ xc)
{
    const int row = blockIdx.x;
    const int tid = threadIdx.x;
    float4* p = (float4*)(x + (size_t)row * 512);
    float4 v = p[tid];
    float s  = v.x + v.y + v.z + v.w;
    float sq = v.x * v.x + v.y * v.y + v.z * v.z + v.w * v.w;
#pragma unroll
    for (int off = 16; off > 0; off >>= 1) {
        s  += __shfl_xor_sync(0xffffffffu, s, off);
        sq += __shfl_xor_sync(0xffffffffu, sq, off);
    }
    __shared__ float ws[4], wq[4];
    __shared__ float stats[2];
    if ((tid & 31) == 0) { ws[tid >> 5] = s; wq[tid >> 5] = sq; }
    __syncthreads();
    if (tid == 0) {
        float S  = ws[0] + ws[1] + ws[2] + ws[3];
        float SQ = wq[0] + wq[1] + wq[2] + wq[3];
        float mu  = S * (1.f / 512.f);
        float var = SQ * (1.f / 512.f) - mu * mu;
        stats[0] = mu;
        stats[1] = rsqrtf(var + 1e-5f);
    }
    __syncthreads();
    float mu = stats[0], inv = stats[1];
    float4 gv = ((const float4*)gamma)[tid];
    float4 bv = ((const float4*)beta)[tid];
    float4 o = make_float4((v.x - mu) * inv * gv.x + bv.x,
                           (v.y - mu) * inv * gv.y + bv.y,
                           (v.z - mu) * inv * gv.z + bv.z,
                           (v.w - mu) * inv * gv.w + bv.w);
    p[tid] = o;
    if (xc) {
        ((uint2*)(xc + (size_t)row * 512))[tid] =
            make_uint2(h2pack(o.x, o.y), h2pack(o.z, o.w));
    }
}

// ---------------------------------------------------------------------------
extern "C" void kernel_launch(void* const* d_in, const int* in_sizes, int n_in,
                              void* d_out, int out_size)
{
    (void)in_sizes; (void)n_in; (void)out_size;
    const float* Q     = (const float*)d_in[0];
    const float* K     = (const float*)d_in[1];
    const float* V     = (const float*)d_in[2];
    const float* Wq    = (const float*)d_in[4];
    const float* Wk    = (const float*)d_in[5];
    const float* Wv    = (const float*)d_in[6];
    const float* Wo    = (const float*)d_in[7];
    const float* bo    = (const float*)d_in[8];
    const float* gamma = (const float*)d_in[9];
    const float* beta  = (const float*)d_in[10];
    const float* W1    = (const float*)d_in[11];
    const float* b1    = (const float*)d_in[12];
    const float* W2    = (const float*)d_in[13];
    const float* b2    = (const float*)d_in[14];
    float* out = (float*)d_out;

    char* base = nullptr;
    cudaGetSymbolAddress((void**)&base, g_scratch);
    const size_t MB = 1024 * 1024;
    __half* qh    = (__half*)(base);
    __half* kh    = (__half*)(base + 4  * MB);
    __half* vh    = (__half*)(base + 8  * MB);
    __half* wqT   = (__half*)(base + 12 * MB);
    __half* wkT   = (__half*)(base + 13 * MB);
    __half* wvT   = (__half*)(base + 14 * MB);
    __half* woT   = (__half*)(base + 15 * MB);
    __half* w1T   = (__half*)(base + 16 * MB);
    __half* w2T   = (__half*)(base + 18 * MB);
    __half* gq    = (__half*)(base + 20 * MB);
    __half* gk    = (__half*)(base + 24 * MB);
    __half* gv    = (__half*)(base + 28 * MB);
    __half* gattn = (__half*)(base + 32 * MB);
    float*  gZ    = (float*) (base + 36 * MB);
    __half* gZc   = (__half*)(base + 44 * MB);
    __half* gff   = (__half*)(base + 48 * MB);

    // log2(e)/sqrt(512): attention uses P = 2^(S)
    const float qscale = 0.06376757604005515f;

    // ---- pre-pass: 2 launches ----
    cvt16_all<<<dim3(GELEMS / (256 * 8), 1, 3), 256>>>(Q, K, V, qh, kh, vh);
    cvtT_all<<<3072, 256>>>(Wq, Wk, Wv, Wo, W1, W2,
                            wqT, wkT, wvT, woT, w1T, w2T);

    // ---- QKV projections (gq pre-scaled) ----
    gemm_qkvh<<<dim3(D_MODEL / 128, M_ROWS / 64, 3), 256>>>(
        qh, kh, vh, wqT, wkT, wvT, gq, gk, gv, M_ROWS, D_MODEL, D_MODEL, qscale);

    // ---- attention over reinterpreted [16, 2048, 64] ----
    attn_tc<<<dim3(16, 16), 256>>>(gq, gk, gv, gattn);

    // ---- Wo projection + bias + residual(V fp32) -> gZ fp32, then LN ----
    gemm_h2f<<<dim3(D_MODEL / 128, M_ROWS / 64), 256>>>(
        gattn, woT, bo, V, gZ, M_ROWS, D_MODEL, D_MODEL);
    ln512v<<<M_ROWS, 128>>>(gZ, gamma, beta, gZc);

    // ---- FFN ----
    gemm_h2h<<<dim3(FF_DIM / 128, M_ROWS / 64), 256>>>(
        gZc, w1T, b1, gff, M_ROWS, FF_DIM, D_MODEL, 1.f);
    gemm_h2f<<<dim3(D_MODEL / 128, M_ROWS / 64), 256>>>(
        gff, w2T, b2, gZ, out, M_ROWS, D_MODEL, FF_DIM);
    ln512v<<<M_ROWS, 128>>>(out, gamma, beta, nullptr);
}

// round 13
// speedup vs baseline: 1.8938x; 1.0603x over previous
#include <cuda_runtime.h>
#include <cuda_fp16.h>

#define M_ROWS 4096
#define D_MODEL 512
#define FF_DIM 2048
#define GELEMS (M_ROWS * D_MODEL)

__device__ __align__(16) float g_scratch[18 * 1024 * 1024];   // 72 MB

// ---------------------------------------------------------------------------
// helpers
// ---------------------------------------------------------------------------
__device__ __forceinline__ unsigned h2pack(float lo, float hi) {
    __half2 h = __floats2half2_rn(lo, hi);
    return *(unsigned*)&h;
}

__device__ __forceinline__ unsigned ex2h2(unsigned x) {
    unsigned d;
    asm("ex2.approx.f16x2 %0, %1;" : "=r"(d) : "r"(x));
    return d;
}

__device__ __forceinline__ void mma_f16(float d[4], const unsigned a[4],
                                        const unsigned b0, const unsigned b1,
                                        const float c[4]) {
    asm volatile(
        "mma.sync.aligned.m16n8k16.row.col.f32.f16.f16.f32 "
        "{%0,%1,%2,%3}, {%4,%5,%6,%7}, {%8,%9}, {%10,%11,%12,%13};"
        : "=f"(d[0]), "=f"(d[1]), "=f"(d[2]), "=f"(d[3])
        : "r"(a[0]), "r"(a[1]), "r"(a[2]), "r"(a[3]),
          "r"(b0), "r"(b1),
          "f"(c[0]), "f"(c[1]), "f"(c[2]), "f"(c[3]));
}

#define LDSM_X4(r, addr) \
    asm volatile("ldmatrix.sync.aligned.m8n8.x4.shared.b16 {%0,%1,%2,%3}, [%4];" \
        : "=r"((r)[0]), "=r"((r)[1]), "=r"((r)[2]), "=r"((r)[3]) : "r"(addr))

#define LDSM_X4_T(r, addr) \
    asm volatile("ldmatrix.sync.aligned.m8n8.x4.trans.shared.b16 {%0,%1,%2,%3}, [%4];" \
        : "=r"((r)[0]), "=r"((r)[1]), "=r"((r)[2]), "=r"((r)[3]) : "r"(addr))

__device__ __forceinline__ unsigned saddr(const void* p) {
    return (unsigned)__cvta_generic_to_shared(p);
}

// ---------------------------------------------------------------------------
// Pre-pass 1: Q,K,V fp32 -> fp16, one launch (z selects buffer)
// ---------------------------------------------------------------------------
__global__ __launch_bounds__(256) void cvt16_all(
    const float* __restrict__ Q, const float* __restrict__ K,
    const float* __restrict__ V,
    __half* __restrict__ qh, __half* __restrict__ kh, __half* __restrict__ vh)
{
    int z = blockIdx.z;
    const float* in = (z == 0) ? Q : (z == 1) ? K : V;
    __half* out     = (z == 0) ? qh : (z == 1) ? kh : vh;
    int i = blockIdx.x * 256 + threadIdx.x;
    const float4* p = (const float4*)in + 2 * (size_t)i;
    float4 a = p[0], b = p[1];
    ((uint4*)out)[i] = make_uint4(h2pack(a.x, a.y), h2pack(a.z, a.w),
                                  h2pack(b.x, b.y), h2pack(b.z, b.w));
}

// ---------------------------------------------------------------------------
// Pre-pass 2: all 6 weight transposes fp32[K,N] -> fp16[N,K], one launch.
// ---------------------------------------------------------------------------
__global__ __launch_bounds__(256) void cvtT_all(
    const float* __restrict__ Wq, const float* __restrict__ Wk,
    const float* __restrict__ Wv, const float* __restrict__ Wo,
    const float* __restrict__ W1, const float* __restrict__ W2,
    __half* __restrict__ wqT, __half* __restrict__ wkT,
    __half* __restrict__ wvT, __half* __restrict__ woT,
    __half* __restrict__ w1T, __half* __restrict__ w2T)
{
    __shared__ float t[32][33];
    int idx = blockIdx.x;
    const float* W; __half* Wt; int K, N, n0, k0;
    if (idx < 1024) {
        int w = idx >> 8, tt = idx & 255;
        K = 512; N = 512;
        W  = (w == 0) ? Wq : (w == 1) ? Wk : (w == 2) ? Wv : Wo;
        Wt = (w == 0) ? wqT : (w == 1) ? wkT : (w == 2) ? wvT : woT;
        n0 = (tt & 15) * 32; k0 = (tt >> 4) * 32;
    } else if (idx < 2048) {
        int tt = idx - 1024;
        K = 512; N = 2048; W = W1; Wt = w1T;
        n0 = (tt & 63) * 32; k0 = (tt >> 6) * 32;
    } else {
        int tt = idx - 2048;
        K = 2048; N = 512; W = W2; Wt = w2T;
        n0 = (tt & 15) * 32; k0 = (tt >> 4) * 32;
    }
    int tx = threadIdx.x & 31, ty = threadIdx.x >> 5;
#pragma unroll
    for (int i = 0; i < 4; i++)
        t[ty + i * 8][tx] = W[(size_t)(k0 + ty + i * 8) * N + n0 + tx];
    __syncthreads();
#pragma unroll
    for (int i = 0; i < 4; i++)
        Wt[(size_t)(n0 + ty + i * 8) * K + k0 + tx] =
            __float2half(t[tx][ty + i * 8]);
}

// ---------------------------------------------------------------------------
// fp16-native GEMM with ldmatrix fragments (unchanged from R11):
// C = A[M,K] @ Wt[N,K]^T. Block 64x128, BK=32, 256 threads, warp tile 32x32.
// ---------------------------------------------------------------------------
template <bool HOUT>
__device__ __forceinline__ void gemm_core_h(
    const __half* __restrict__ A, const __half* __restrict__ Wt,
    const float* __restrict__ bias, const float* __restrict__ res,
    void* __restrict__ Cout, int M, int N, int K, float oscale)
{
    __shared__ unsigned As[64 * 20];
    __shared__ unsigned Bs[128 * 20];

    const int tid  = threadIdx.x;
    const int lane = tid & 31;
    const int warp = tid >> 5;
    const int wm   = warp & 1;
    const int wn   = warp >> 1;
    const int gr   = lane >> 2;
    const int gc   = lane & 3;
    const int li   = lane & 7;
    const int seg  = lane >> 3;

    const int bm = blockIdx.y * 64;
    const int bn = blockIdx.x * 128;

    const int arow = tid >> 2;
    const int ac4  = (tid & 3) * 4;

    const unsigned aBase =
        saddr(&As[(wm * 32 + li + (seg & 1) * 8) * 20 + (seg >> 1) * 4]);
    const unsigned bBase =
        saddr(&Bs[(wn * 32 + li + (seg >> 1) * 8) * 20 + (seg & 1) * 4]);

    float acc[2][4][4] = {};

    for (int k0 = 0; k0 < K; k0 += 32) {
        *(uint4*)&As[arow * 20 + ac4] =
            *(const uint4*)(A + (size_t)(bm + arow) * K + k0 + ac4 * 2);
#pragma unroll
        for (int i = 0; i < 2; i++) {
            int u = tid + i * 256;
            int br = u >> 2, bc4 = (u & 3) * 4;
            *(uint4*)&Bs[br * 20 + bc4] =
                *(const uint4*)(Wt + (size_t)(bn + br) * K + k0 + bc4 * 2);
        }
        __syncthreads();

#pragma unroll
        for (int kk = 0; kk < 2; kk++) {
            unsigned a0[4], a1[4], bb0[4], bb1[4];
            LDSM_X4(a0,  aBase + (kk * 8) * 4);
            LDSM_X4(a1,  aBase + (16 * 20 + kk * 8) * 4);
            LDSM_X4(bb0, bBase + (kk * 8) * 4);
            LDSM_X4(bb1, bBase + (16 * 20 + kk * 8) * 4);
            mma_f16(acc[0][0], a0, bb0[0], bb0[1], acc[0][0]);
            mma_f16(acc[0][1], a0, bb0[2], bb0[3], acc[0][1]);
            mma_f16(acc[0][2], a0, bb1[0], bb1[1], acc[0][2]);
            mma_f16(acc[0][3], a0, bb1[2], bb1[3], acc[0][3]);
            mma_f16(acc[1][0], a1, bb0[0], bb0[1], acc[1][0]);
            mma_f16(acc[1][1], a1, bb0[2], bb0[3], acc[1][1]);
            mma_f16(acc[1][2], a1, bb1[0], bb1[1], acc[1][2]);
            mma_f16(acc[1][3], a1, bb1[2], bb1[3], acc[1][3]);
        }
        __syncthreads();
    }

#pragma unroll
    for (int mt = 0; mt < 2; mt++) {
#pragma unroll
        for (int nt = 0; nt < 4; nt++) {
            int r0  = bm + wm * 32 + mt * 16 + gr;
            int col = bn + wn * 32 + nt * 8 + 2 * gc;
            float v0 = acc[mt][nt][0] * oscale;
            float v1 = acc[mt][nt][1] * oscale;
            float v2 = acc[mt][nt][2] * oscale;
            float v3 = acc[mt][nt][3] * oscale;
            if (bias) {
                float b0 = bias[col], b1 = bias[col + 1];
                v0 += b0; v1 += b1; v2 += b0; v3 += b1;
            }
            if (HOUT) {
                __half* C = (__half*)Cout;
                *(unsigned*)(C + (size_t)r0 * N + col)       = h2pack(v0, v1);
                *(unsigned*)(C + (size_t)(r0 + 8) * N + col) = h2pack(v2, v3);
            } else {
                float* C = (float*)Cout;
                if (res) {
                    float2 r0v = *(const float2*)(res + (size_t)r0 * N + col);
                    float2 r1v = *(const float2*)(res + (size_t)(r0 + 8) * N + col);
                    v0 += r0v.x; v1 += r0v.y; v2 += r1v.x; v3 += r1v.y;
                }
                *(float2*)(C + (size_t)r0 * N + col)       = make_float2(v0, v1);
                *(float2*)(C + (size_t)(r0 + 8) * N + col) = make_float2(v2, v3);
            }
        }
    }
}

__global__ __launch_bounds__(256) void gemm_h2h(
    const __half* __restrict__ A, const __half* __restrict__ Wt,
    const float* __restrict__ bias, __half* __restrict__ C,
    int M, int N, int K, float sc)
{
    gemm_core_h<true>(A, Wt, bias, nullptr, C, M, N, K, sc);
}

__global__ __launch_bounds__(256) void gemm_h2f(
    const __half* __restrict__ A, const __half* __restrict__ Wt,
    const float* __restrict__ bias, const float* __restrict__ res,
    float* __restrict__ C, int M, int N, int K)
{
    gemm_core_h<false>(A, Wt, bias, res, C, M, N, K, 1.f);
}

__global__ __launch_bounds__(256) void gemm_qkvh(
    const __half* __restrict__ Qh, const __half* __restrict__ Kh,
    const __half* __restrict__ Vh,
    const __half* __restrict__ wqT, const __half* __restrict__ wkT,
    const __half* __restrict__ wvT,
    __half* __restrict__ gq, __half* __restrict__ gk, __half* __restrict__ gv,
    int M, int N, int K, float qscale)
{
    int z = blockIdx.z;
    const __half* A  = (z == 0) ? Qh : (z == 1) ? Kh : Vh;
    const __half* Wt = (z == 0) ? wqT : (z == 1) ? wkT : wvT;
    __half* C        = (z == 0) ? gq : (z == 1) ? gk : gv;
    float sc         = (z == 0) ? qscale : 1.f;
    gemm_core_h<true>(A, Wt, nullptr, nullptr, C, M, N, K, sc);
}

// ---------------------------------------------------------------------------
// fp16 flash attention. V fragments now via ldmatrix.x4.trans on plain
// row-major V tiles (staging = raw copy, no byte_perm; 64 LDS -> 16 LDSM
// per warp per tile). K frags via ldmatrix (R11). P = 2^S via ex2.f16x2;
// denominator via mma against all-ones B.
// ---------------------------------------------------------------------------
__global__ __launch_bounds__(256) void attn_tc(
    const __half* __restrict__ qp, const __half* __restrict__ kp,
    const __half* __restrict__ vp, __half* __restrict__ op)
{
    __shared__ unsigned Qs[128 * 36];
    __shared__ unsigned Ks[64 * 36];
    __shared__ unsigned Vs[64 * 36];

    const int tid  = threadIdx.x;
    const int lane = tid & 31;
    const int warp = tid >> 5;
    const int gr   = lane >> 2;
    const int gc   = lane & 3;
    const int li   = lane & 7;
    const int seg  = lane >> 3;
    const int g    = blockIdx.y;
    const int q0   = blockIdx.x * 128;
    const unsigned ONES = 0x3C003C00u;

    const __half* qg = qp + ((size_t)g * 2048 + q0) * 64;
#pragma unroll
    for (int i = 0; i < 4; i++) {
        int u = tid + i * 256;
        int row = u >> 3, wc = (u & 7) * 4;
        *(uint4*)&Qs[row * 36 + wc] =
            *(const uint4*)(qg + (size_t)row * 64 + wc * 2);
    }
    __syncthreads();

    unsigned qa[4][4];
    const int r = warp * 16 + gr;
#pragma unroll
    for (int kk = 0; kk < 4; kk++) {
        int j = kk * 8 + gc;
        qa[kk][0] = Qs[r * 36 + j];
        qa[kk][1] = Qs[(r + 8) * 36 + j];
        qa[kk][2] = Qs[r * 36 + j + 4];
        qa[kk][3] = Qs[(r + 8) * 36 + j + 4];
    }

    // ldmatrix bases. K (non-trans): row = li + (seg>>1)*8 [n], word col = (seg&1)*4 [k].
    // V (trans): row = li + (seg&1)*8 [j/key], word col = (seg>>1)*4 [n].
    const unsigned kBase =
        saddr(&Ks[(li + (seg >> 1) * 8) * 36 + (seg & 1) * 4]);
    const unsigned vBase =
        saddr(&Vs[(li + (seg & 1) * 8) * 36 + (seg >> 1) * 4]);

    float oacc[8][4];
#pragma unroll
    for (int nt = 0; nt < 8; nt++)
#pragma unroll
        for (int i = 0; i < 4; i++) oacc[nt][i] = 0.f;
    float psacc[4] = {0.f, 0.f, 0.f, 0.f};

    for (int kt = 0; kt < 32; kt++) {
        __syncthreads();
        const __half* kg = kp + ((size_t)g * 2048 + kt * 64) * 64;
        const __half* vg = vp + ((size_t)g * 2048 + kt * 64) * 64;
#pragma unroll
        for (int i = 0; i < 2; i++) {
            int u = tid + i * 256;
            int row = u >> 3, wc = (u & 7) * 4;
            *(uint4*)&Ks[row * 36 + wc] =
                *(const uint4*)(kg + (size_t)row * 64 + wc * 2);
            *(uint4*)&Vs[row * 36 + wc] =
                *(const uint4*)(vg + (size_t)row * 64 + wc * 2);
        }
        __syncthreads();

        // S = Q @ K^T
        float sacc[8][4];
#pragma unroll
        for (int nt = 0; nt < 8; nt++)
#pragma unroll
            for (int i = 0; i < 4; i++) sacc[nt][i] = 0.f;
#pragma unroll
        for (int kk = 0; kk < 4; kk++) {
#pragma unroll
            for (int ntp = 0; ntp < 4; ntp++) {
                unsigned kb[4];
                LDSM_X4(kb, kBase + (ntp * 16 * 36 + kk * 8) * 4);
                mma_f16(sacc[2 * ntp],     qa[kk], kb[0], kb[1], sacc[2 * ntp]);
                mma_f16(sacc[2 * ntp + 1], qa[kk], kb[2], kb[3], sacc[2 * ntp + 1]);
            }
        }

        // P = 2^S packed directly into A-fragments
        unsigned pa[4][4];
#pragma unroll
        for (int nt = 0; nt < 8; nt++) {
            int kk = nt >> 1;
            int hi = nt & 1;
            pa[kk][hi * 2 + 0] = ex2h2(h2pack(sacc[nt][0], sacc[nt][1]));
            pa[kk][hi * 2 + 1] = ex2h2(h2pack(sacc[nt][2], sacc[nt][3]));
        }

        // O += P @ V : V B-frags via ldmatrix.trans (m0=b0, m1=b1 of nt;
        // m2=b0, m3=b1 of nt+1)
#pragma unroll
        for (int kk = 0; kk < 4; kk++) {
#pragma unroll
            for (int ntp = 0; ntp < 4; ntp++) {
                unsigned vb[4];
                LDSM_X4_T(vb, vBase + (kk * 16 * 36 + ntp * 8) * 4);
                mma_f16(oacc[2 * ntp],     pa[kk], vb[0], vb[1], oacc[2 * ntp]);
                mma_f16(oacc[2 * ntp + 1], pa[kk], vb[2], vb[3], oacc[2 * ntp + 1]);
            }
            mma_f16(psacc, pa[kk], ONES, ONES, psacc);
        }
    }

    float inv0 = 1.f / psacc[0];
    float inv1 = 1.f / psacc[2];
    int rr = q0 + warp * 16 + gr;
    unsigned* og = (unsigned*)(op + ((size_t)g * 2048 + rr) * 64);
#pragma unroll
    for (int nt = 0; nt < 8; nt++) {
        og[nt * 4 + gc]          = h2pack(oacc[nt][0] * inv0, oacc[nt][1] * inv0);
        og[8 * 32 + nt * 4 + gc] = h2pack(oacc[nt][2] * inv1, oacc[nt][3] * inv1);
    }
}

// ---------------------------------------------------------------------------
// Layernorm (fp32 in-place, optional fp16 copy out).
// ---------------------------------------------------------------------------
__global__ __launch_bounds__(128) void ln512v(
    float* __restrict__ x, const float* __restrict__ gamma,
    const float* __restrict__ beta, __half* __restrict__ xc)
{
    const int row = blockIdx.x;
    const int tid = threadIdx.x;
    float4* p = (float4*)(x + (size_t)row * 512);
    float4 v = p[tid];
    float s  = v.x + v.y + v.z + v.w;
    float sq = v.x * v.x + v.y * v.y + v.z * v.z + v.w * v.w;
#pragma unroll
    for (int off = 16; off > 0; off >>= 1) {
        s  += __shfl_xor_sync(0xffffffffu, s, off);
        sq += __shfl_xor_sync(0xffffffffu, sq, off);
    }
    __shared__ float ws[4], wq[4];
    __shared__ float stats[2];
    if ((tid & 31) == 0) { ws[tid >> 5] = s; wq[tid >> 5] = sq; }
    __syncthreads();
    if (tid == 0) {
        float S  = ws[0] + ws[1] + ws[2] + ws[3];
        float SQ = wq[0] + wq[1] + wq[2] + wq[3];
        float mu  = S * (1.f / 512.f);
        float var = SQ * (1.f / 512.f) - mu * mu;
        stats[0] = mu;
        stats[1] = rsqrtf(var + 1e-5f);
    }
    __syncthreads();
    float mu = stats[0], inv = stats[1];
    float4 gv = ((const float4*)gamma)[tid];
    float4 bv = ((const float4*)beta)[tid];
    float4 o = make_float4((v.x - mu) * inv * gv.x + bv.x,
                           (v.y - mu) * inv * gv.y + bv.y,
                           (v.z - mu) * inv * gv.z + bv.z,
                           (v.w - mu) * inv * gv.w + bv.w);
    p[tid] = o;
    if (xc) {
        ((uint2*)(xc + (size_t)row * 512))[tid] =
            make_uint2(h2pack(o.x, o.y), h2pack(o.z, o.w));
    }
}

// ---------------------------------------------------------------------------
extern "C" void kernel_launch(void* const* d_in, const int* in_sizes, int n_in,
                              void* d_out, int out_size)
{
    (void)in_sizes; (void)n_in; (void)out_size;
    const float* Q     = (const float*)d_in[0];
    const float* K     = (const float*)d_in[1];
    const float* V     = (const float*)d_in[2];
    const float* Wq    = (const float*)d_in[4];
    const float* Wk    = (const float*)d_in[5];
    const float* Wv    = (const float*)d_in[6];
    const float* Wo    = (const float*)d_in[7];
    const float* bo    = (const float*)d_in[8];
    const float* gamma = (const float*)d_in[9];
    const float* beta  = (const float*)d_in[10];
    const float* W1    = (const float*)d_in[11];
    const float* b1    = (const float*)d_in[12];
    const float* W2    = (const float*)d_in[13];
    const float* b2    = (const float*)d_in[14];
    float* out = (float*)d_out;

    char* base = nullptr;
    cudaGetSymbolAddress((void**)&base, g_scratch);
    const size_t MB = 1024 * 1024;
    __half* qh    = (__half*)(base);
    __half* kh    = (__half*)(base + 4  * MB);
    __half* vh    = (__half*)(base + 8  * MB);
    __half* wqT   = (__half*)(base + 12 * MB);
    __half* wkT   = (__half*)(base + 13 * MB);
    __half* wvT   = (__half*)(base + 14 * MB);
    __half* woT   = (__half*)(base + 15 * MB);
    __half* w1T   = (__half*)(base + 16 * MB);
    __half* w2T   = (__half*)(base + 18 * MB);
    __half* gq    = (__half*)(base + 20 * MB);
    __half* gk    = (__half*)(base + 24 * MB);
    __half* gv    = (__half*)(base + 28 * MB);
    __half* gattn = (__half*)(base + 32 * MB);
    float*  gZ    = (float*) (base + 36 * MB);
    __half* gZc   = (__half*)(base + 44 * MB);
    __half* gff   = (__half*)(base + 48 * MB);

    // log2(e)/sqrt(512): attention uses P = 2^S
    const float qscale = 0.06376757604005515f;

    // ---- pre-pass: 2 launches ----
    cvt16_all<<<dim3(GELEMS / (256 * 8), 1, 3), 256>>>(Q, K, V, qh, kh, vh);
    cvtT_all<<<3072, 256>>>(Wq, Wk, Wv, Wo, W1, W2,
                            wqT, wkT, wvT, woT, w1T, w2T);

    // ---- QKV projections (gq pre-scaled) ----
    gemm_qkvh<<<dim3(D_MODEL / 128, M_ROWS / 64, 3), 256>>>(
        qh, kh, vh, wqT, wkT, wvT, gq, gk, gv, M_ROWS, D_MODEL, D_MODEL, qscale);

    // ---- attention over reinterpreted [16, 2048, 64] ----
    attn_tc<<<dim3(16, 16), 256>>>(gq, gk, gv, gattn);

    // ---- Wo projection + bias + residual(V fp32) -> gZ fp32, then LN ----
    gemm_h2f<<<dim3(D_MODEL / 128, M_ROWS / 64), 256>>>(
        gattn, woT, bo, V, gZ, M_ROWS, D_MODEL, D_MODEL);
    ln512v<<<M_ROWS, 128>>>(gZ, gamma, beta, gZc);

    // ---- FFN ----
    gemm_h2h<<<dim3(FF_DIM / 128, M_ROWS / 64), 256>>>(
        gZc, w1T, b1, gff, M_ROWS, FF_DIM, D_MODEL, 1.f);
    gemm_h2f<<<dim3(D_MODEL / 128, M_ROWS / 64), 256>>>(
        gff, w2T, b2, gZ, out, M_ROWS, D_MODEL, FF_DIM);
    ln512v<<<M_ROWS, 128>>>(out, gamma, beta, nullptr);
}

// round 14
// speedup vs baseline: 2.1525x; 1.1366x over previous
#include <cuda_runtime.h>
#include <cuda_fp16.h>

#define M_ROWS 4096
#define D_MODEL 512
#define FF_DIM 2048
#define GELEMS (M_ROWS * D_MODEL)

__device__ __align__(16) float g_scratch[18 * 1024 * 1024];   // 72 MB

// ---------------------------------------------------------------------------
// helpers
// ---------------------------------------------------------------------------
__device__ __forceinline__ unsigned h2pack(float lo, float hi) {
    __half2 h = __floats2half2_rn(lo, hi);
    return *(unsigned*)&h;
}

__device__ __forceinline__ unsigned ex2h2(unsigned x) {
    unsigned d;
    asm("ex2.approx.f16x2 %0, %1;" : "=r"(d) : "r"(x));
    return d;
}

__device__ __forceinline__ void mma_f16(float d[4], const unsigned a[4],
                                        const unsigned b0, const unsigned b1,
                                        const float c[4]) {
    asm volatile(
        "mma.sync.aligned.m16n8k16.row.col.f32.f16.f16.f32 "
        "{%0,%1,%2,%3}, {%4,%5,%6,%7}, {%8,%9}, {%10,%11,%12,%13};"
        : "=f"(d[0]), "=f"(d[1]), "=f"(d[2]), "=f"(d[3])
        : "r"(a[0]), "r"(a[1]), "r"(a[2]), "r"(a[3]),
          "r"(b0), "r"(b1),
          "f"(c[0]), "f"(c[1]), "f"(c[2]), "f"(c[3]));
}

#define LDSM_X4(r, addr) \
    asm volatile("ldmatrix.sync.aligned.m8n8.x4.shared.b16 {%0,%1,%2,%3}, [%4];" \
        : "=r"((r)[0]), "=r"((r)[1]), "=r"((r)[2]), "=r"((r)[3]) : "r"(addr))

#define LDSM_X4_T(r, addr) \
    asm volatile("ldmatrix.sync.aligned.m8n8.x4.trans.shared.b16 {%0,%1,%2,%3}, [%4];" \
        : "=r"((r)[0]), "=r"((r)[1]), "=r"((r)[2]), "=r"((r)[3]) : "r"(addr))

__device__ __forceinline__ unsigned saddr(const void* p) {
    return (unsigned)__cvta_generic_to_shared(p);
}

__device__ __forceinline__ void cp16(unsigned dst, const void* src) {
    asm volatile("cp.async.cg.shared.global [%0], [%1], 16;"
                 :: "r"(dst), "l"(src) : "memory");
}
#define CP_COMMIT() asm volatile("cp.async.commit_group;" ::: "memory")
template <int N> __device__ __forceinline__ void cp_wait() {
    asm volatile("cp.async.wait_group %0;" :: "n"(N) : "memory");
}

// ---------------------------------------------------------------------------
// Pre-pass 1: Q,K,V fp32 -> fp16
// ---------------------------------------------------------------------------
__global__ __launch_bounds__(256) void cvt16_all(
    const float* __restrict__ Q, const float* __restrict__ K,
    const float* __restrict__ V,
    __half* __restrict__ qh, __half* __restrict__ kh, __half* __restrict__ vh)
{
    int z = blockIdx.z;
    const float* in = (z == 0) ? Q : (z == 1) ? K : V;
    __half* out     = (z == 0) ? qh : (z == 1) ? kh : vh;
    int i = blockIdx.x * 256 + threadIdx.x;
    const float4* p = (const float4*)in + 2 * (size_t)i;
    float4 a = p[0], b = p[1];
    ((uint4*)out)[i] = make_uint4(h2pack(a.x, a.y), h2pack(a.z, a.w),
                                  h2pack(b.x, b.y), h2pack(b.z, b.w));
}

// ---------------------------------------------------------------------------
// Pre-pass 2: 6 weight transposes fp32[K,N] -> fp16[N,K], one launch.
// ---------------------------------------------------------------------------
__global__ __launch_bounds__(256) void cvtT_all(
    const float* __restrict__ Wq, const float* __restrict__ Wk,
    const float* __restrict__ Wv, const float* __restrict__ Wo,
    const float* __restrict__ W1, const float* __restrict__ W2,
    __half* __restrict__ wqT, __half* __restrict__ wkT,
    __half* __restrict__ wvT, __half* __restrict__ woT,
    __half* __restrict__ w1T, __half* __restrict__ w2T)
{
    __shared__ float t[32][33];
    int idx = blockIdx.x;
    const float* W; __half* Wt; int K, N, n0, k0;
    if (idx < 1024) {
        int w = idx >> 8, tt = idx & 255;
        K = 512; N = 512;
        W  = (w == 0) ? Wq : (w == 1) ? Wk : (w == 2) ? Wv : Wo;
        Wt = (w == 0) ? wqT : (w == 1) ? wkT : (w == 2) ? wvT : woT;
        n0 = (tt & 15) * 32; k0 = (tt >> 4) * 32;
    } else if (idx < 2048) {
        int tt = idx - 1024;
        K = 512; N = 2048; W = W1; Wt = w1T;
        n0 = (tt & 63) * 32; k0 = (tt >> 6) * 32;
    } else {
        int tt = idx - 2048;
        K = 2048; N = 512; W = W2; Wt = w2T;
        n0 = (tt & 15) * 32; k0 = (tt >> 4) * 32;
    }
    int tx = threadIdx.x & 31, ty = threadIdx.x >> 5;
#pragma unroll
    for (int i = 0; i < 4; i++)
        t[ty + i * 8][tx] = W[(size_t)(k0 + ty + i * 8) * N + n0 + tx];
    __syncthreads();
#pragma unroll
    for (int i = 0; i < 4; i++)
        Wt[(size_t)(n0 + ty + i * 8) * K + k0 + tx] =
            __float2half(t[tx][ty + i * 8]);
}

// ---------------------------------------------------------------------------
// fp16 GEMM, cp.async double-buffered: C = A[M,K] @ Wt[N,K]^T.
// Block 64x128, BK=32, 256 threads, warp tile 32x32. ldmatrix fragments.
// ---------------------------------------------------------------------------
#define AS_W (64 * 20)
#define BS_W (128 * 20)

template <bool HOUT>
__device__ __forceinline__ void gemm_core_h(
    const __half* __restrict__ A, const __half* __restrict__ Wt,
    const float* __restrict__ bias, const float* __restrict__ res,
    void* __restrict__ Cout, int M, int N, int K, float oscale)
{
    __shared__ unsigned As[2 * AS_W];
    __shared__ unsigned Bs[2 * BS_W];

    const int tid  = threadIdx.x;
    const int lane = tid & 31;
    const int warp = tid >> 5;
    const int wm   = warp & 1;
    const int wn   = warp >> 1;
    const int gr   = lane >> 2;
    const int gc   = lane & 3;
    const int li   = lane & 7;
    const int seg  = lane >> 3;

    const int bm = blockIdx.y * 64;
    const int bn = blockIdx.x * 128;

    const int arow = tid >> 2;
    const int ac4  = (tid & 3) * 4;
    const int br0  = tid >> 2;            // B row for i=0
    const int br1  = br0 + 64;            // B row for i=1
    const int bc4  = (tid & 3) * 4;

    // cp.async destinations (buffer 0)
    const unsigned aDst  = saddr(&As[arow * 20 + ac4]);
    const unsigned bDst0 = saddr(&Bs[br0 * 20 + bc4]);
    const unsigned bDst1 = saddr(&Bs[br1 * 20 + bc4]);
    // global sources (k0 = 0)
    const __half* aSrc  = A  + (size_t)(bm + arow) * K + ac4 * 2;
    const __half* bSrc0 = Wt + (size_t)(bn + br0) * K + bc4 * 2;
    const __half* bSrc1 = Wt + (size_t)(bn + br1) * K + bc4 * 2;

    const unsigned aBase =
        saddr(&As[(wm * 32 + li + (seg & 1) * 8) * 20 + (seg >> 1) * 4]);
    const unsigned bBase =
        saddr(&Bs[(wn * 32 + li + (seg >> 1) * 8) * 20 + (seg & 1) * 4]);

    float acc[2][4][4] = {};
    const int T = K >> 5;

    // prologue: stage 0 -> buffer 0
    cp16(aDst, aSrc);
    cp16(bDst0, bSrc0);
    cp16(bDst1, bSrc1);
    CP_COMMIT();

    for (int s = 0; s < T; s++) {
        int buf = s & 1;
        if (s + 1 < T) {
            int nb = buf ^ 1;
            int k0 = (s + 1) << 5;
            cp16(aDst  + nb * AS_W * 4, aSrc  + k0);
            cp16(bDst0 + nb * BS_W * 4, bSrc0 + k0);
            cp16(bDst1 + nb * BS_W * 4, bSrc1 + k0);
            CP_COMMIT();
            cp_wait<1>();
        } else {
            cp_wait<0>();
        }
        __syncthreads();

        const unsigned aB = aBase + buf * AS_W * 4;
        const unsigned bB = bBase + buf * BS_W * 4;
#pragma unroll
        for (int kk = 0; kk < 2; kk++) {
            unsigned a0[4], a1[4], bb0[4], bb1[4];
            LDSM_X4(a0,  aB + (kk * 8) * 4);
            LDSM_X4(a1,  aB + (16 * 20 + kk * 8) * 4);
            LDSM_X4(bb0, bB + (kk * 8) * 4);
            LDSM_X4(bb1, bB + (16 * 20 + kk * 8) * 4);
            mma_f16(acc[0][0], a0, bb0[0], bb0[1], acc[0][0]);
            mma_f16(acc[0][1], a0, bb0[2], bb0[3], acc[0][1]);
            mma_f16(acc[0][2], a0, bb1[0], bb1[1], acc[0][2]);
            mma_f16(acc[0][3], a0, bb1[2], bb1[3], acc[0][3]);
            mma_f16(acc[1][0], a1, bb0[0], bb0[1], acc[1][0]);
            mma_f16(acc[1][1], a1, bb0[2], bb0[3], acc[1][1]);
            mma_f16(acc[1][2], a1, bb1[0], bb1[1], acc[1][2]);
            mma_f16(acc[1][3], a1, bb1[2], bb1[3], acc[1][3]);
        }
        __syncthreads();
    }

#pragma unroll
    for (int mt = 0; mt < 2; mt++) {
#pragma unroll
        for (int nt = 0; nt < 4; nt++) {
            int r0  = bm + wm * 32 + mt * 16 + gr;
            int col = bn + wn * 32 + nt * 8 + 2 * gc;
            float v0 = acc[mt][nt][0] * oscale;
            float v1 = acc[mt][nt][1] * oscale;
            float v2 = acc[mt][nt][2] * oscale;
            float v3 = acc[mt][nt][3] * oscale;
            if (bias) {
                float b0 = bias[col], b1 = bias[col + 1];
                v0 += b0; v1 += b1; v2 += b0; v3 += b1;
            }
            if (HOUT) {
                __half* C = (__half*)Cout;
                *(unsigned*)(C + (size_t)r0 * N + col)       = h2pack(v0, v1);
                *(unsigned*)(C + (size_t)(r0 + 8) * N + col) = h2pack(v2, v3);
            } else {
                float* C = (float*)Cout;
                if (res) {
                    float2 r0v = *(const float2*)(res + (size_t)r0 * N + col);
                    float2 r1v = *(const float2*)(res + (size_t)(r0 + 8) * N + col);
                    v0 += r0v.x; v1 += r0v.y; v2 += r1v.x; v3 += r1v.y;
                }
                *(float2*)(C + (size_t)r0 * N + col)       = make_float2(v0, v1);
                *(float2*)(C + (size_t)(r0 + 8) * N + col) = make_float2(v2, v3);
            }
        }
    }
}

__global__ __launch_bounds__(256) void gemm_h2h(
    const __half* __restrict__ A, const __half* __restrict__ Wt,
    const float* __restrict__ bias, __half* __restrict__ C,
    int M, int N, int K, float sc)
{
    gemm_core_h<true>(A, Wt, bias, nullptr, C, M, N, K, sc);
}

__global__ __launch_bounds__(256) void gemm_h2f(
    const __half* __restrict__ A, const __half* __restrict__ Wt,
    const float* __restrict__ bias, const float* __restrict__ res,
    float* __restrict__ C, int M, int N, int K)
{
    gemm_core_h<false>(A, Wt, bias, res, C, M, N, K, 1.f);
}

__global__ __launch_bounds__(256) void gemm_qkvh(
    const __half* __restrict__ Qh, const __half* __restrict__ Kh,
    const __half* __restrict__ Vh,
    const __half* __restrict__ wqT, const __half* __restrict__ wkT,
    const __half* __restrict__ wvT,
    __half* __restrict__ gq, __half* __restrict__ gk, __half* __restrict__ gv,
    int M, int N, int K, float qscale)
{
    int z = blockIdx.z;
    const __half* A  = (z == 0) ? Qh : (z == 1) ? Kh : Vh;
    const __half* Wt = (z == 0) ? wqT : (z == 1) ? wkT : wvT;
    __half* C        = (z == 0) ? gq : (z == 1) ? gk : gv;
    float sc         = (z == 0) ? qscale : 1.f;
    gemm_core_h<true>(A, Wt, nullptr, nullptr, C, M, N, K, sc);
}

// ---------------------------------------------------------------------------
// fp16 flash attention, cp.async double-buffered K/V tiles.
// K frags via ldmatrix, V frags via ldmatrix.trans, P = 2^S via ex2.f16x2,
// denominator via mma against all-ones B. Dynamic smem (54 KB).
// ---------------------------------------------------------------------------
#define KV_W (64 * 36)
#define ATTN_SMEM ((128 * 36 + 4 * KV_W) * 4)

__global__ __launch_bounds__(256) void attn_tc(
    const __half* __restrict__ qp, const __half* __restrict__ kp,
    const __half* __restrict__ vp, __half* __restrict__ op)
{
    extern __shared__ unsigned asmem[];
    unsigned* Qs = asmem;                 // 128 x 36
    unsigned* Kb = Qs + 128 * 36;         // 2 x 64 x 36
    unsigned* Vb = Kb + 2 * KV_W;         // 2 x 64 x 36

    const int tid  = threadIdx.x;
    const int lane = tid & 31;
    const int warp = tid >> 5;
    const int gr   = lane >> 2;
    const int gc   = lane & 3;
    const int li   = lane & 7;
    const int seg  = lane >> 3;
    const int g    = blockIdx.y;
    const int q0   = blockIdx.x * 128;
    const unsigned ONES = 0x3C003C00u;

    // staging indices (per thread): 2 uint4 each for K and V per tile
    const int srow0 = tid >> 3;           // rows 0..31
    const int srow1 = srow0 + 32;         // rows 32..63
    const int swc   = (tid & 7) * 4;
    const unsigned kDst0 = saddr(&Kb[srow0 * 36 + swc]);
    const unsigned kDst1 = saddr(&Kb[srow1 * 36 + swc]);
    const unsigned vDst0 = saddr(&Vb[srow0 * 36 + swc]);
    const unsigned vDst1 = saddr(&Vb[srow1 * 36 + swc]);

    const __half* qg = qp + ((size_t)g * 2048 + q0) * 64;
#pragma unroll
    for (int i = 0; i < 4; i++) {
        int u = tid + i * 256;
        int row = u >> 3, wc = (u & 7) * 4;
        *(uint4*)&Qs[row * 36 + wc] =
            *(const uint4*)(qg + (size_t)row * 64 + wc * 2);
    }

    // prologue: stage K/V tile 0 into buffer 0
    {
        const __half* kg = kp + (size_t)g * 2048 * 64;
        const __half* vg = vp + (size_t)g * 2048 * 64;
        cp16(kDst0, kg + (size_t)srow0 * 64 + swc * 2);
        cp16(kDst1, kg + (size_t)srow1 * 64 + swc * 2);
        cp16(vDst0, vg + (size_t)srow0 * 64 + swc * 2);
        cp16(vDst1, vg + (size_t)srow1 * 64 + swc * 2);
        CP_COMMIT();
    }
    __syncthreads();

    unsigned qa[4][4];
    const int r = warp * 16 + gr;
#pragma unroll
    for (int kk = 0; kk < 4; kk++) {
        int j = kk * 8 + gc;
        qa[kk][0] = Qs[r * 36 + j];
        qa[kk][1] = Qs[(r + 8) * 36 + j];
        qa[kk][2] = Qs[r * 36 + j + 4];
        qa[kk][3] = Qs[(r + 8) * 36 + j + 4];
    }

    const unsigned kBase =
        saddr(&Kb[(li + (seg >> 1) * 8) * 36 + (seg & 1) * 4]);
    const unsigned vBase =
        saddr(&Vb[(li + (seg & 1) * 8) * 36 + (seg >> 1) * 4]);

    float oacc[8][4];
#pragma unroll
    for (int nt = 0; nt < 8; nt++)
#pragma unroll
        for (int i = 0; i < 4; i++) oacc[nt][i] = 0.f;
    float psacc[4] = {0.f, 0.f, 0.f, 0.f};

    for (int kt = 0; kt < 32; kt++) {
        int buf = kt & 1;
        if (kt + 1 < 32) {
            int nb = buf ^ 1;
            const __half* kg = kp + ((size_t)g * 2048 + (kt + 1) * 64) * 64;
            const __half* vg = vp + ((size_t)g * 2048 + (kt + 1) * 64) * 64;
            cp16(kDst0 + nb * KV_W * 4, kg + (size_t)srow0 * 64 + swc * 2);
            cp16(kDst1 + nb * KV_W * 4, kg + (size_t)srow1 * 64 + swc * 2);
            cp16(vDst0 + nb * KV_W * 4, vg + (size_t)srow0 * 64 + swc * 2);
            cp16(vDst1 + nb * KV_W * 4, vg + (size_t)srow1 * 64 + swc * 2);
            CP_COMMIT();
            cp_wait<1>();
        } else {
            cp_wait<0>();
        }
        __syncthreads();

        const unsigned kB = kBase + buf * KV_W * 4;
        const unsigned vB = vBase + buf * KV_W * 4;

        // S = Q @ K^T
        float sacc[8][4];
#pragma unroll
        for (int nt = 0; nt < 8; nt++)
#pragma unroll
            for (int i = 0; i < 4; i++) sacc[nt][i] = 0.f;
#pragma unroll
        for (int kk = 0; kk < 4; kk++) {
#pragma unroll
            for (int ntp = 0; ntp < 4; ntp++) {
                unsigned kb[4];
                LDSM_X4(kb, kB + (ntp * 16 * 36 + kk * 8) * 4);
                mma_f16(sacc[2 * ntp],     qa[kk], kb[0], kb[1], sacc[2 * ntp]);
                mma_f16(sacc[2 * ntp + 1], qa[kk], kb[2], kb[3], sacc[2 * ntp + 1]);
            }
        }

        // P = 2^S packed directly into A-fragments
        unsigned pa[4][4];
#pragma unroll
        for (int nt = 0; nt < 8; nt++) {
            int kk = nt >> 1;
            int hi = nt & 1;
            pa[kk][hi * 2 + 0] = ex2h2(h2pack(sacc[nt][0], sacc[nt][1]));
            pa[kk][hi * 2 + 1] = ex2h2(h2pack(sacc[nt][2], sacc[nt][3]));
        }

        // O += P @ V (V frags via ldmatrix.trans); denom += P @ ones
#pragma unroll
        for (int kk = 0; kk < 4; kk++) {
#pragma unroll
            for (int ntp = 0; ntp < 4; ntp++) {
                unsigned vb[4];
                LDSM_X4_T(vb, vB + (kk * 16 * 36 + ntp * 8) * 4);
                mma_f16(oacc[2 * ntp],     pa[kk], vb[0], vb[1], oacc[2 * ntp]);
                mma_f16(oacc[2 * ntp + 1], pa[kk], vb[2], vb[3], oacc[2 * ntp + 1]);
            }
            mma_f16(psacc, pa[kk], ONES, ONES, psacc);
        }
        __syncthreads();
    }

    float inv0 = 1.f / psacc[0];
    float inv1 = 1.f / psacc[2];
    int rr = q0 + warp * 16 + gr;
    unsigned* og = (unsigned*)(op + ((size_t)g * 2048 + rr) * 64);
#pragma unroll
    for (int nt = 0; nt < 8; nt++) {
        og[nt * 4 + gc]          = h2pack(oacc[nt][0] * inv0, oacc[nt][1] * inv0);
        og[8 * 32 + nt * 4 + gc] = h2pack(oacc[nt][2] * inv1, oacc[nt][3] * inv1);
    }
}

// ---------------------------------------------------------------------------
// Layernorm (fp32 in-place, optional fp16 copy out).
// ---------------------------------------------------------------------------
__global__ __launch_bounds__(128) void ln512v(
    float* __restrict__ x, const float* __restrict__ gamma,
    const float* __restrict__ beta, __half* __restrict__ xc)
{
    const int row = blockIdx.x;
    const int tid = threadIdx.x;
    float4* p = (float4*)(x + (size_t)row * 512);
    float4 v = p[tid];
    float s  = v.x + v.y + v.z + v.w;
    float sq = v.x * v.x + v.y * v.y + v.z * v.z + v.w * v.w;
#pragma unroll
    for (int off = 16; off > 0; off >>= 1) {
        s  += __shfl_xor_sync(0xffffffffu, s, off);
        sq += __shfl_xor_sync(0xffffffffu, sq, off);
    }
    __shared__ float ws[4], wq[4];
    __shared__ float stats[2];
    if ((tid & 31) == 0) { ws[tid >> 5] = s; wq[tid >> 5] = sq; }
    __syncthreads();
    if (tid == 0) {
        float S  = ws[0] + ws[1] + ws[2] + ws[3];
        float SQ = wq[0] + wq[1] + wq[2] + wq[3];
        float mu  = S * (1.f / 512.f);
        float var = SQ * (1.f / 512.f) - mu * mu;
        stats[0] = mu;
        stats[1] = rsqrtf(var + 1e-5f);
    }
    __syncthreads();
    float mu = stats[0], inv = stats[1];
    float4 gv = ((const float4*)gamma)[tid];
    float4 bv = ((const float4*)beta)[tid];
    float4 o = make_float4((v.x - mu) * inv * gv.x + bv.x,
                           (v.y - mu) * inv * gv.y + bv.y,
                           (v.z - mu) * inv * gv.z + bv.z,
                           (v.w - mu) * inv * gv.w + bv.w);
    p[tid] = o;
    if (xc) {
        ((uint2*)(xc + (size_t)row * 512))[tid] =
            make_uint2(h2pack(o.x, o.y), h2pack(o.z, o.w));
    }
}

// ---------------------------------------------------------------------------
extern "C" void kernel_launch(void* const* d_in, const int* in_sizes, int n_in,
                              void* d_out, int out_size)
{
    (void)in_sizes; (void)n_in; (void)out_size;
    const float* Q     = (const float*)d_in[0];
    const float* K     = (const float*)d_in[1];
    const float* V     = (const float*)d_in[2];
    const float* Wq    = (const float*)d_in[4];
    const float* Wk    = (const float*)d_in[5];
    const float* Wv    = (const float*)d_in[6];
    const float* Wo    = (const float*)d_in[7];
    const float* bo    = (const float*)d_in[8];
    const float* gamma = (const float*)d_in[9];
    const float* beta  = (const float*)d_in[10];
    const float* W1    = (const float*)d_in[11];
    const float* b1    = (const float*)d_in[12];
    const float* W2    = (const float*)d_in[13];
    const float* b2    = (const float*)d_in[14];
    float* out = (float*)d_out;

    char* base = nullptr;
    cudaGetSymbolAddress((void**)&base, g_scratch);
    const size_t MB = 1024 * 1024;
    __half* qh    = (__half*)(base);
    __half* kh    = (__half*)(base + 4  * MB);
    __half* vh    = (__half*)(base + 8  * MB);
    __half* wqT   = (__half*)(base + 12 * MB);
    __half* wkT   = (__half*)(base + 13 * MB);
    __half* wvT   = (__half*)(base + 14 * MB);
    __half* woT   = (__half*)(base + 15 * MB);
    __half* w1T   = (__half*)(base + 16 * MB);
    __half* w2T   = (__half*)(base + 18 * MB);
    __half* gq    = (__half*)(base + 20 * MB);
    __half* gk    = (__half*)(base + 24 * MB);
    __half* gv    = (__half*)(base + 28 * MB);
    __half* gattn = (__half*)(base + 32 * MB);
    float*  gZ    = (float*) (base + 36 * MB);
    __half* gZc   = (__half*)(base + 44 * MB);
    __half* gff   = (__half*)(base + 48 * MB);

    // log2(e)/sqrt(512): attention uses P = 2^S
    const float qscale = 0.06376757604005515f;

    cudaFuncSetAttribute(attn_tc,
        cudaFuncAttributeMaxDynamicSharedMemorySize, ATTN_SMEM);

    // ---- pre-pass: 2 launches ----
    cvt16_all<<<dim3(GELEMS / (256 * 8), 1, 3), 256>>>(Q, K, V, qh, kh, vh);
    cvtT_all<<<3072, 256>>>(Wq, Wk, Wv, Wo, W1, W2,
                            wqT, wkT, wvT, woT, w1T, w2T);

    // ---- QKV projections (gq pre-scaled) ----
    gemm_qkvh<<<dim3(D_MODEL / 128, M_ROWS / 64, 3), 256>>>(
        qh, kh, vh, wqT, wkT, wvT, gq, gk, gv, M_ROWS, D_MODEL, D_MODEL, qscale);

    // ---- attention over reinterpreted [16, 2048, 64] ----
    attn_tc<<<dim3(16, 16), 256, ATTN_SMEM>>>(gq, gk, gv, gattn);

    // ---- Wo projection + bias + residual(V fp32) -> gZ fp32, then LN ----
    gemm_h2f<<<dim3(D_MODEL / 128, M_ROWS / 64), 256>>>(
        gattn, woT, bo, V, gZ, M_ROWS, D_MODEL, D_MODEL);
    ln512v<<<M_ROWS, 128>>>(gZ, gamma, beta, gZc);

    // ---- FFN ----
    gemm_h2h<<<dim3(FF_DIM / 128, M_ROWS / 64), 256>>>(
        gZc, w1T, b1, gff, M_ROWS, FF_DIM, D_MODEL, 1.f);
    gemm_h2f<<<dim3(D_MODEL / 128, M_ROWS / 64), 256>>>(
        gff, w2T, b2, gZ, out, M_ROWS, D_MODEL, FF_DIM);
    ln512v<<<M_ROWS, 128>>>(out, gamma, beta, nullptr);
}